// round 1
// baseline (speedup 1.0000x reference)
#include <cuda_runtime.h>
#include <cstdint>

#define HIDDEN 128
#define NREL   8
#define MAXN   100000
#define MAXE   600000
#define KTOT   (HIDDEN * (NREL + 1))   // 1152 packed output columns (self + 8 relations)

// ---------------- device scratch (static: no allocations allowed) ----------------
__device__ int   g_is64;                                  // 1 if edge arrays are int64
__device__ int   g_deg[MAXN * NREL];                      // per (node, relation) in-degree
__device__ float g_T[(size_t)MAXN * (NREL * HIDDEN)];     // relation-transformed features, 409.6 MB
__device__ float g_out[(size_t)MAXN * HIDDEN];            // pre-activation accumulator, 51.2 MB
__device__ float g_Wcat[HIDDEN * KTOT];                   // packed B matrix, k-major: Wcat[k][j]

// ---------------- dtype detection for edge arrays ----------------
__global__ void k_detect(const void* ei) {
    // If data is genuinely int64, indices are < 2^31. If it's int32 read as int64,
    // pairs combine into values >= 2^32 with overwhelming probability.
    const long long* p = (const long long*)ei;
    int ok64 = 1;
    for (int i = 0; i < 16; i++) {
        long long v = p[i];
        if (v < 0 || v >= (1LL << 31)) ok64 = 0;
    }
    g_is64 = ok64;
}

__device__ __forceinline__ int edge_val(const void* arr, int idx) {
    if (g_is64) return (int)((const long long*)arr)[idx];
    return ((const int*)arr)[idx];
}

// ---------------- init: zero degree counts + pack Wcat ----------------
__global__ void k_init(const float* __restrict__ Wself,
                       const float* __restrict__ Wrel, int N) {
    int stride = gridDim.x * blockDim.x;
    int i = blockIdx.x * blockDim.x + threadIdx.x;
    int nd = N * NREL;
    for (int t = i; t < nd; t += stride) g_deg[t] = 0;
    for (int t = i; t < HIDDEN * KTOT; t += stride) {
        int k = t / KTOT;
        int j = t % KTOT;
        float v;
        if (j < HIDDEN) v = Wself[j * HIDDEN + k];                 // W_self[j][k]
        else            v = Wrel[(size_t)(j - HIDDEN) * HIDDEN + k]; // W_rel[r][jj][k]
        g_Wcat[t] = v;
    }
}

// ---------------- per-(dst, relation) degree counting ----------------
__global__ void k_count(const void* ei, const void* et, int E) {
    int e = blockIdx.x * blockDim.x + threadIdx.x;
    if (e >= E) return;
    int dst = edge_val(ei, E + e);
    int r   = edge_val(et, e);
    atomicAdd(&g_deg[dst * NREL + r], 1);
}

// ---------------- fused GEMM: [M,128] x [128,1152] -> out (cols 0..127, +bias) & T ----------------
#define BM 128
#define BN 128
#define BK 16
__global__ __launch_bounds__(256, 2)
void k_gemm(const float* __restrict__ h, const float* __restrict__ b_self, int M) {
    __shared__ float As[BK][BM];
    __shared__ float Bs[BK][BN];
    int bm = blockIdx.x, bn = blockIdx.y;
    int tid = threadIdx.x;
    int tx = tid & 15;   // 16 col groups
    int ty = tid >> 4;   // 16 row groups
    int rowBase = bm * BM;

    float acc[8][8];
#pragma unroll
    for (int i = 0; i < 8; i++)
#pragma unroll
        for (int j = 0; j < 8; j++) acc[i][j] = 0.f;

    for (int k0 = 0; k0 < HIDDEN; k0 += BK) {
        // A tile: 128 rows x 16 k -> 512 float4 loads
#pragma unroll
        for (int i = 0; i < 2; i++) {
            int idx = tid + i * 256;
            int m = idx >> 2;
            int kq = idx & 3;
            int row = rowBase + m;
            float4 v = make_float4(0.f, 0.f, 0.f, 0.f);
            if (row < M) v = *(const float4*)&h[(size_t)row * HIDDEN + k0 + kq * 4];
            As[kq * 4 + 0][m] = v.x;
            As[kq * 4 + 1][m] = v.y;
            As[kq * 4 + 2][m] = v.z;
            As[kq * 4 + 3][m] = v.w;
        }
        // B tile: 16 k x 128 cols, contiguous per k row
#pragma unroll
        for (int i = 0; i < 2; i++) {
            int idx = tid + i * 256;
            int k = idx >> 5;
            int nq = idx & 31;
            *(float4*)&Bs[k][nq * 4] =
                *(const float4*)&g_Wcat[(size_t)(k0 + k) * KTOT + bn * BN + nq * 4];
        }
        __syncthreads();
#pragma unroll
        for (int k = 0; k < BK; k++) {
            float a[8], b[8];
            *(float4*)(a)     = *(float4*)&As[k][ty * 8];
            *(float4*)(a + 4) = *(float4*)&As[k][ty * 8 + 4];
            *(float4*)(b)     = *(float4*)&Bs[k][tx * 8];
            *(float4*)(b + 4) = *(float4*)&Bs[k][tx * 8 + 4];
#pragma unroll
            for (int i = 0; i < 8; i++)
#pragma unroll
                for (int j = 0; j < 8; j++) acc[i][j] += a[i] * b[j];
        }
        __syncthreads();
    }

    int rowT = rowBase + ty * 8;
    if (bn == 0) {
        float bias[8];
        *(float4*)(bias)     = *(const float4*)&b_self[tx * 8];
        *(float4*)(bias + 4) = *(const float4*)&b_self[tx * 8 + 4];
#pragma unroll
        for (int i = 0; i < 8; i++) {
            int row = rowT + i;
            if (row < M) {
                float4 v0 = make_float4(acc[i][0] + bias[0], acc[i][1] + bias[1],
                                        acc[i][2] + bias[2], acc[i][3] + bias[3]);
                float4 v1 = make_float4(acc[i][4] + bias[4], acc[i][5] + bias[5],
                                        acc[i][6] + bias[6], acc[i][7] + bias[7]);
                *(float4*)&g_out[(size_t)row * HIDDEN + tx * 8]     = v0;
                *(float4*)&g_out[(size_t)row * HIDDEN + tx * 8 + 4] = v1;
            }
        }
    } else {
        int colBase = (bn - 1) * BN + tx * 8;   // column within T's 1024
#pragma unroll
        for (int i = 0; i < 8; i++) {
            int row = rowT + i;
            if (row < M) {
                float4 v0 = make_float4(acc[i][0], acc[i][1], acc[i][2], acc[i][3]);
                float4 v1 = make_float4(acc[i][4], acc[i][5], acc[i][6], acc[i][7]);
                *(float4*)&g_T[(size_t)row * (NREL * HIDDEN) + colBase]     = v0;
                *(float4*)&g_T[(size_t)row * (NREL * HIDDEN) + colBase + 4] = v1;
            }
        }
    }
}

// ---------------- edge scatter: out[dst] += T[src, r] / deg ----------------
__global__ void k_scatter(const void* ei, const void* et, int E) {
    int gwarp = (blockIdx.x * blockDim.x + threadIdx.x) >> 5;
    int lane = threadIdx.x & 31;
    if (gwarp >= E) return;
    int e = gwarp;
    int src = edge_val(ei, e);
    int dst = edge_val(ei, E + e);
    int r   = edge_val(et, e);
    int deg = g_deg[dst * NREL + r];          // >= 1 because this edge exists
    float inv = 1.0f / (float)deg;
    float4 v = *(const float4*)&g_T[(size_t)src * (NREL * HIDDEN) + r * HIDDEN + lane * 4];
    v.x *= inv; v.y *= inv; v.z *= inv; v.w *= inv;
    atomicAdd((float4*)&g_out[(size_t)dst * HIDDEN + lane * 4], v);  // RED.128, sm_90+
}

// ---------------- ReLU + LayerNorm + affine -> d_out ----------------
__global__ void k_ln(const float* __restrict__ gamma, const float* __restrict__ beta,
                     float* __restrict__ out, int N) {
    int gwarp = (blockIdx.x * blockDim.x + threadIdx.x) >> 5;
    int lane = threadIdx.x & 31;
    if (gwarp >= N) return;
    float4 v = *(const float4*)&g_out[(size_t)gwarp * HIDDEN + lane * 4];
    v.x = fmaxf(v.x, 0.f); v.y = fmaxf(v.y, 0.f);
    v.z = fmaxf(v.z, 0.f); v.w = fmaxf(v.w, 0.f);
    float s = v.x + v.y + v.z + v.w;
#pragma unroll
    for (int o = 16; o > 0; o >>= 1) s += __shfl_xor_sync(0xffffffffu, s, o);
    float mu = s * (1.0f / HIDDEN);
    float dx = v.x - mu, dy = v.y - mu, dz = v.z - mu, dw = v.w - mu;
    float ss = dx * dx + dy * dy + dz * dz + dw * dw;
#pragma unroll
    for (int o = 16; o > 0; o >>= 1) ss += __shfl_xor_sync(0xffffffffu, ss, o);
    float rs = rsqrtf(ss * (1.0f / HIDDEN) + 1e-5f);
    float4 g = *(const float4*)&gamma[lane * 4];
    float4 b = *(const float4*)&beta[lane * 4];
    float4 y = make_float4(dx * rs * g.x + b.x, dy * rs * g.y + b.y,
                           dz * rs * g.z + b.z, dw * rs * g.w + b.w);
    *(float4*)&out[(size_t)gwarp * HIDDEN + lane * 4] = y;
}

// ---------------- launch ----------------
extern "C" void kernel_launch(void* const* d_in, const int* in_sizes, int n_in,
                              void* d_out, int out_size) {
    const float* h      = (const float*)d_in[0];
    const void*  ei     = d_in[1];
    const void*  et     = d_in[2];
    const float* Wself  = (const float*)d_in[3];
    const float* bself  = (const float*)d_in[4];
    const float* Wrel   = (const float*)d_in[5];
    const float* gamma  = (const float*)d_in[6];
    const float* beta   = (const float*)d_in[7];
    float* out = (float*)d_out;

    int N = in_sizes[0] / HIDDEN;
    int E = in_sizes[2];

    k_detect<<<1, 1>>>(ei);
    k_init<<<256, 256>>>(Wself, Wrel, N);
    k_count<<<(E + 255) / 256, 256>>>(ei, et, E);

    dim3 ggrid((N + BM - 1) / BM, KTOT / BN);
    k_gemm<<<ggrid, 256>>>(h, bself, N);

    int sblocks = (E * 32 + 255) / 256;
    k_scatter<<<sblocks, 256>>>(ei, et, E);

    int lblocks = (N * 32 + 255) / 256;
    k_ln<<<lblocks, 256>>>(gamma, beta, out, N);
}

// round 3
// speedup vs baseline: 1.9315x; 1.9315x over previous
#include <cuda_runtime.h>
#include <cuda_bf16.h>
#include <cstdint>

#define HIDDEN 128
#define NREL   8
#define MAXN   100000

// ---------------- device scratch ----------------
__device__ int   g_is64;
__device__ int   g_deg[MAXN * NREL];
__device__ __align__(16) float g_T[(size_t)MAXN * 1024];      // relation-transformed feats
__device__ __align__(16) float g_out[(size_t)MAXN * HIDDEN];  // pre-activation accumulator
__device__ __align__(16) __nv_bfloat16 g_Ah[(size_t)MAXN * HIDDEN];
__device__ __align__(16) __nv_bfloat16 g_Al[(size_t)MAXN * HIDDEN];
__device__ __align__(16) __nv_bfloat16 g_Bh[1152 * HIDDEN];   // [out_col][k]
__device__ __align__(16) __nv_bfloat16 g_Bl[1152 * HIDDEN];

// ---------------- helpers ----------------
__device__ __forceinline__ uint32_t smem_u32(const void* p) {
    uint32_t a;
    asm("{ .reg .u64 t; cvta.to.shared.u64 t, %1; cvt.u32.u64 %0, t; }" : "=r"(a) : "l"(p));
    return a;
}
__device__ __forceinline__ void ldsm4(uint32_t* r, uint32_t addr) {
    asm volatile("ldmatrix.sync.aligned.m8n8.x4.shared.b16 {%0,%1,%2,%3}, [%4];"
                 : "=r"(r[0]), "=r"(r[1]), "=r"(r[2]), "=r"(r[3]) : "r"(addr));
}
__device__ __forceinline__ void mma16816(float* d, const uint32_t* a, const uint32_t* b) {
    asm volatile("mma.sync.aligned.m16n8k16.row.col.f32.bf16.bf16.f32 "
                 "{%0,%1,%2,%3}, {%4,%5,%6,%7}, {%8,%9}, {%0,%1,%2,%3};"
                 : "+f"(d[0]), "+f"(d[1]), "+f"(d[2]), "+f"(d[3])
                 : "r"(a[0]), "r"(a[1]), "r"(a[2]), "r"(a[3]), "r"(b[0]), "r"(b[1]));
}
#define CP16(dst, src) asm volatile("cp.async.cg.shared.global [%0], [%1], 16;" :: "r"(dst), "l"(src))
#define CP_COMMIT()    asm volatile("cp.async.commit_group;")

static __device__ __forceinline__ unsigned short f2bf(float f) {
    __nv_bfloat16 b = __float2bfloat16(f);
    return *reinterpret_cast<unsigned short*>(&b);
}
static __device__ __forceinline__ float bfu2f(unsigned short u) {
    __nv_bfloat16 b;
    *reinterpret_cast<unsigned short*>(&b) = u;
    return __bfloat162float(b);
}

// ---------------- edge dtype detect ----------------
__global__ void k_detect(const void* ei) {
    const long long* p = (const long long*)ei;
    int ok64 = 1;
    for (int i = 0; i < 16; i++) {
        long long v = p[i];
        if (v < 0 || v >= (1LL << 31)) ok64 = 0;
    }
    g_is64 = ok64;
}
__device__ __forceinline__ int edge_val(const void* arr, int idx) {
    if (g_is64) return (int)((const long long*)arr)[idx];
    return ((const int*)arr)[idx];
}

// ---------------- init: zero deg + bf16-split weights ----------------
__global__ void k_init(const float* __restrict__ Wself, const float* __restrict__ Wrel, int N) {
    int stride = gridDim.x * blockDim.x;
    int i0 = blockIdx.x * blockDim.x + threadIdx.x;
    int nd = N * NREL;
    for (int t = i0; t < nd; t += stride) g_deg[t] = 0;
    for (int t = i0; t < 18432; t += stride) {   // 1152*128/8 chunks of 8 floats
        const float* src = (t < 2048) ? (Wself + (size_t)t * 8) : (Wrel + (size_t)(t - 2048) * 8);
        float4 a = *(const float4*)src;
        float4 b = *(const float4*)(src + 4);
        float x[8] = {a.x, a.y, a.z, a.w, b.x, b.y, b.z, b.w};
        unsigned short hs[8], ls[8];
#pragma unroll
        for (int j = 0; j < 8; j++) {
            hs[j] = f2bf(x[j]);
            ls[j] = f2bf(x[j] - bfu2f(hs[j]));
        }
        uint4 H = make_uint4(hs[0] | (hs[1] << 16), hs[2] | (hs[3] << 16),
                             hs[4] | (hs[5] << 16), hs[6] | (hs[7] << 16));
        uint4 L = make_uint4(ls[0] | (ls[1] << 16), ls[2] | (ls[3] << 16),
                             ls[4] | (ls[5] << 16), ls[6] | (ls[7] << 16));
        *(uint4*)(g_Bh + (size_t)t * 8) = H;
        *(uint4*)(g_Bl + (size_t)t * 8) = L;
    }
}

// ---------------- bf16-split node features ----------------
__global__ void k_prep_h(const float* __restrict__ h, int N) {
    int idx = blockIdx.x * blockDim.x + threadIdx.x;   // chunk of 8 floats
    if (idx >= N * 16) return;
    const float* src = h + (size_t)idx * 8;
    float4 a = *(const float4*)src;
    float4 b = *(const float4*)(src + 4);
    float x[8] = {a.x, a.y, a.z, a.w, b.x, b.y, b.z, b.w};
    unsigned short hs[8], ls[8];
#pragma unroll
    for (int j = 0; j < 8; j++) {
        hs[j] = f2bf(x[j]);
        ls[j] = f2bf(x[j] - bfu2f(hs[j]));
    }
    uint4 H = make_uint4(hs[0] | (hs[1] << 16), hs[2] | (hs[3] << 16),
                         hs[4] | (hs[5] << 16), hs[6] | (hs[7] << 16));
    uint4 L = make_uint4(ls[0] | (ls[1] << 16), ls[2] | (ls[3] << 16),
                         ls[4] | (ls[5] << 16), ls[6] | (ls[7] << 16));
    *(uint4*)(g_Ah + (size_t)idx * 8) = H;
    *(uint4*)(g_Al + (size_t)idx * 8) = L;
}

// ---------------- per-(dst, relation) degree counting ----------------
__global__ void k_count(const void* ei, const void* et, int E) {
    int e = blockIdx.x * blockDim.x + threadIdx.x;
    if (e >= E) return;
    int dst = edge_val(ei, E + e);
    int r   = edge_val(et, e);
    atomicAdd(&g_deg[dst * NREL + r], 1);
}

// ---------------- mma.sync GEMM: [M,128] x [128,1152], 3-term bf16 split ----------------
// One CTA per 128-row block. A (Ah+Al) resident in smem; loop 9 N-tiles of 128,
// B double-buffered via cp.async. 8 warps = 4(m) x 2(n); warp tile 32x64.
// smem: A at 0 (2 x 32KB), B at 65536 (2 stages x 2 x 32KB) -> 192KB total.
#define SMEM_TOTAL 196608

__global__ void __launch_bounds__(256, 1) k_gemm(const float* __restrict__ bself, int M) {
    extern __shared__ char smem[];
    uint32_t sb = smem_u32(smem);
    int tid = threadIdx.x, wid = tid >> 5, lane = tid & 31;
    int bx = blockIdx.x;
    int wm = wid >> 1, wn = wid & 1;
    int g = lane >> 2, tig = lane & 3;

    // ---- A tiles (both halves), rows clamped (OOB rows never stored) ----
#pragma unroll
    for (int hf = 0; hf < 2; hf++) {
        const __nv_bfloat16* gsrc = hf ? g_Al : g_Ah;
#pragma unroll
        for (int i = 0; i < 8; i++) {
            int id = i * 256 + tid;
            int r = id >> 4, c8 = id & 15;
            int grow = bx * 128 + r;
            if (grow >= M) grow = M - 1;
            const void* src = gsrc + (size_t)grow * 128 + c8 * 8;
            uint32_t dst = sb + hf * 32768 + r * 256 + ((c8 ^ (r & 7)) << 4);
            CP16(dst, src);
        }
    }
    // ---- B stage loader ----
    auto cpB = [&](int bn, int s) {
#pragma unroll
        for (int hf = 0; hf < 2; hf++) {
            const __nv_bfloat16* gsrc = hf ? g_Bl : g_Bh;
#pragma unroll
            for (int i = 0; i < 8; i++) {
                int id = i * 256 + tid;
                int r = id >> 4, c8 = id & 15;
                const void* src = gsrc + (size_t)(bn * 128 + r) * 128 + c8 * 8;
                uint32_t dst = sb + 65536 + s * 65536 + hf * 32768 + r * 256 + ((c8 ^ (r & 7)) << 4);
                CP16(dst, src);
            }
        }
    };
    cpB(0, 0);
    CP_COMMIT();           // G0: A + B0
    cpB(1, 1);
    CP_COMMIT();           // G1: B1

    for (int bn = 0; bn < 9; bn++) {
        if (bn == 8) asm volatile("cp.async.wait_group 0;");
        else         asm volatile("cp.async.wait_group 1;");
        __syncthreads();

        uint32_t aBase = sb;
        uint32_t bBase = sb + 65536 + (bn & 1) * 65536;

        float acc[2][8][4];
#pragma unroll
        for (int mf = 0; mf < 2; mf++)
#pragma unroll
            for (int nb = 0; nb < 8; nb++)
#pragma unroll
                for (int q = 0; q < 4; q++) acc[mf][nb][q] = 0.f;

#pragma unroll
        for (int ks = 0; ks < 8; ks++) {
            uint32_t ah[2][4], al[2][4], bh[8][2], bl[8][2];
#pragma unroll
            for (int mf = 0; mf < 2; mf++) {
                int row = wm * 32 + mf * 16 + (lane & 15);
                int c8 = ks * 2 + (lane >> 4);
                uint32_t ad = aBase + row * 256 + ((c8 ^ (row & 7)) << 4);
                ldsm4(ah[mf], ad);
                ldsm4(al[mf], ad + 32768);
            }
#pragma unroll
            for (int p = 0; p < 4; p++) {
                int j = wn * 64 + p * 16 + (lane >> 4) * 8 + (lane & 7);
                int c8 = ks * 2 + ((lane >> 3) & 1);
                uint32_t bd = bBase + j * 256 + ((c8 ^ (j & 7)) << 4);
                uint32_t t[4];
                ldsm4(t, bd);
                bh[2 * p][0] = t[0]; bh[2 * p][1] = t[1];
                bh[2 * p + 1][0] = t[2]; bh[2 * p + 1][1] = t[3];
                ldsm4(t, bd + 32768);
                bl[2 * p][0] = t[0]; bl[2 * p][1] = t[1];
                bl[2 * p + 1][0] = t[2]; bl[2 * p + 1][1] = t[3];
            }
#pragma unroll
            for (int mf = 0; mf < 2; mf++)
#pragma unroll
                for (int nb = 0; nb < 8; nb++) {
                    mma16816(acc[mf][nb], ah[mf], bh[nb]);
                    mma16816(acc[mf][nb], ah[mf], bl[nb]);
                    mma16816(acc[mf][nb], al[mf], bh[nb]);
                }
        }

        __syncthreads();                 // all warps done reading buffer (bn&1)
        if (bn < 7) {
            cpB(bn + 2, bn & 1);         // prefetch into just-freed buffer
            CP_COMMIT();
        }

        // ---- epilogue ----
#pragma unroll
        for (int mf = 0; mf < 2; mf++) {
            int row0 = bx * 128 + wm * 32 + mf * 16 + g;
#pragma unroll
            for (int half = 0; half < 2; half++) {
                int row = row0 + half * 8;
                if (row < M) {
                    if (bn == 0) {
                        float* o = g_out + (size_t)row * HIDDEN + wn * 64;
#pragma unroll
                        for (int nb = 0; nb < 8; nb++) {
                            int col = nb * 8 + tig * 2;
                            float2 v;
                            v.x = acc[mf][nb][half * 2 + 0] + __ldg(bself + wn * 64 + col);
                            v.y = acc[mf][nb][half * 2 + 1] + __ldg(bself + wn * 64 + col + 1);
                            *(float2*)(o + col) = v;
                        }
                    } else {
                        float* o = g_T + (size_t)row * 1024 + (bn - 1) * 128 + wn * 64;
#pragma unroll
                        for (int nb = 0; nb < 8; nb++) {
                            int col = nb * 8 + tig * 2;
                            float2 v;
                            v.x = acc[mf][nb][half * 2 + 0];
                            v.y = acc[mf][nb][half * 2 + 1];
                            *(float2*)(o + col) = v;
                        }
                    }
                }
            }
        }
    }
}

// ---------------- edge scatter: out[dst] += T[src, r] / deg ----------------
__global__ void k_scatter(const void* ei, const void* et, int E) {
    int gwarp = (blockIdx.x * blockDim.x + threadIdx.x) >> 5;
    int lane = threadIdx.x & 31;
    if (gwarp >= E) return;
    int e = gwarp;
    int src = edge_val(ei, e);
    int dst = edge_val(ei, E + e);
    int r   = edge_val(et, e);
    int deg = g_deg[dst * NREL + r];
    float inv = 1.0f / (float)deg;
    float4 v = *(const float4*)&g_T[(size_t)src * 1024 + r * HIDDEN + lane * 4];
    v.x *= inv; v.y *= inv; v.z *= inv; v.w *= inv;
    atomicAdd((float4*)&g_out[(size_t)dst * HIDDEN + lane * 4], v);
}

// ---------------- ReLU + LayerNorm ----------------
__global__ void k_ln(const float* __restrict__ gamma, const float* __restrict__ beta,
                     float* __restrict__ out, int N) {
    int gwarp = (blockIdx.x * blockDim.x + threadIdx.x) >> 5;
    int lane = threadIdx.x & 31;
    if (gwarp >= N) return;
    float4 v = *(const float4*)&g_out[(size_t)gwarp * HIDDEN + lane * 4];
    v.x = fmaxf(v.x, 0.f); v.y = fmaxf(v.y, 0.f);
    v.z = fmaxf(v.z, 0.f); v.w = fmaxf(v.w, 0.f);
    float s = v.x + v.y + v.z + v.w;
#pragma unroll
    for (int o = 16; o > 0; o >>= 1) s += __shfl_xor_sync(0xffffffffu, s, o);
    float mu = s * (1.0f / HIDDEN);
    float dx = v.x - mu, dy = v.y - mu, dz = v.z - mu, dw = v.w - mu;
    float ss = dx * dx + dy * dy + dz * dz + dw * dw;
#pragma unroll
    for (int o = 16; o > 0; o >>= 1) ss += __shfl_xor_sync(0xffffffffu, ss, o);
    float rs = rsqrtf(ss * (1.0f / HIDDEN) + 1e-5f);
    float4 gg = *(const float4*)&gamma[lane * 4];
    float4 bb = *(const float4*)&beta[lane * 4];
    float4 y = make_float4(dx * rs * gg.x + bb.x, dy * rs * gg.y + bb.y,
                           dz * rs * gg.z + bb.z, dw * rs * gg.w + bb.w);
    *(float4*)&out[(size_t)gwarp * HIDDEN + lane * 4] = y;
}

// ---------------- launch ----------------
extern "C" void kernel_launch(void* const* d_in, const int* in_sizes, int n_in,
                              void* d_out, int out_size) {
    const float* h     = (const float*)d_in[0];
    const void*  ei    = d_in[1];
    const void*  et    = d_in[2];
    const float* Wself = (const float*)d_in[3];
    const float* bself = (const float*)d_in[4];
    const float* Wrel  = (const float*)d_in[5];
    const float* gamma = (const float*)d_in[6];
    const float* beta  = (const float*)d_in[7];
    float* out = (float*)d_out;

    int N = in_sizes[0] / HIDDEN;
    int E = in_sizes[2];

    cudaFuncSetAttribute(k_gemm, cudaFuncAttributeMaxDynamicSharedMemorySize, SMEM_TOTAL);

    k_detect<<<1, 1>>>(ei);
    k_init<<<256, 256>>>(Wself, Wrel, N);
    k_prep_h<<<(N * 16 + 255) / 256, 256>>>(h, N);
    k_count<<<(E + 255) / 256, 256>>>(ei, et, E);

    int mblocks = (N + 127) / 128;
    k_gemm<<<mblocks, 256, SMEM_TOTAL>>>(bself, N);

    int sblocks = (E * 32 + 255) / 256;
    k_scatter<<<sblocks, 256>>>(ei, et, E);

    int lblocks = (N * 32 + 255) / 256;
    k_ln<<<lblocks, 256>>>(gamma, beta, out, N);
}

// round 4
// speedup vs baseline: 2.1118x; 1.0934x over previous
#include <cuda_runtime.h>
#include <cuda_bf16.h>
#include <cstdint>

#define HIDDEN 128
#define NREL   8
#define MAXN   100000

// ---------------- device scratch ----------------
__device__ int   g_is64;
__device__ int   g_deg[MAXN * NREL];
__device__ __align__(16) float g_T[(size_t)MAXN * 1024];      // relation-transformed feats
__device__ __align__(16) float g_out[(size_t)MAXN * HIDDEN];  // pre-activation accumulator
__device__ __align__(16) __nv_bfloat16 g_Ah[(size_t)MAXN * HIDDEN];
__device__ __align__(16) __nv_bfloat16 g_Al[(size_t)MAXN * HIDDEN];
__device__ __align__(16) __nv_bfloat16 g_Bh[1152 * HIDDEN];   // [out_col][k]
__device__ __align__(16) __nv_bfloat16 g_Bl[1152 * HIDDEN];

// ---------------- helpers ----------------
__device__ __forceinline__ uint32_t smem_u32(const void* p) {
    uint32_t a;
    asm("{ .reg .u64 t; cvta.to.shared.u64 t, %1; cvt.u32.u64 %0, t; }" : "=r"(a) : "l"(p));
    return a;
}
__device__ __forceinline__ void ldsm4(uint32_t* r, uint32_t addr) {
    asm volatile("ldmatrix.sync.aligned.m8n8.x4.shared.b16 {%0,%1,%2,%3}, [%4];"
                 : "=r"(r[0]), "=r"(r[1]), "=r"(r[2]), "=r"(r[3]) : "r"(addr));
}
__device__ __forceinline__ void mma16816(float* d, const uint32_t* a, const uint32_t* b) {
    asm volatile("mma.sync.aligned.m16n8k16.row.col.f32.bf16.bf16.f32 "
                 "{%0,%1,%2,%3}, {%4,%5,%6,%7}, {%8,%9}, {%0,%1,%2,%3};"
                 : "+f"(d[0]), "+f"(d[1]), "+f"(d[2]), "+f"(d[3])
                 : "r"(a[0]), "r"(a[1]), "r"(a[2]), "r"(a[3]), "r"(b[0]), "r"(b[1]));
}
#define CP16(dst, src) asm volatile("cp.async.cg.shared.global [%0], [%1], 16;" :: "r"(dst), "l"(src))
#define CP_COMMIT()    asm volatile("cp.async.commit_group;")

static __device__ __forceinline__ unsigned short f2bf(float f) {
    __nv_bfloat16 b = __float2bfloat16(f);
    return *reinterpret_cast<unsigned short*>(&b);
}
static __device__ __forceinline__ float bfu2f(unsigned short u) {
    __nv_bfloat16 b;
    *reinterpret_cast<unsigned short*>(&b) = u;
    return __bfloat162float(b);
}

// ---------------- edge dtype detect ----------------
__global__ void k_detect(const void* ei) {
    const long long* p = (const long long*)ei;
    int ok64 = 1;
    for (int i = 0; i < 16; i++) {
        long long v = p[i];
        if (v < 0 || v >= (1LL << 31)) ok64 = 0;
    }
    g_is64 = ok64;
}
__device__ __forceinline__ int edge_val(const void* arr, int idx) {
    if (g_is64) return (int)((const long long*)arr)[idx];
    return ((const int*)arr)[idx];
}

// ---------------- init: zero deg + bf16-split weights ----------------
__global__ void k_init(const float* __restrict__ Wself, const float* __restrict__ Wrel, int N) {
    int stride = gridDim.x * blockDim.x;
    int i0 = blockIdx.x * blockDim.x + threadIdx.x;
    int nd = N * NREL;
    for (int t = i0; t < nd; t += stride) g_deg[t] = 0;
    for (int t = i0; t < 18432; t += stride) {   // 1152*128/8 chunks of 8 floats
        const float* src = (t < 2048) ? (Wself + (size_t)t * 8) : (Wrel + (size_t)(t - 2048) * 8);
        float4 a = *(const float4*)src;
        float4 b = *(const float4*)(src + 4);
        float x[8] = {a.x, a.y, a.z, a.w, b.x, b.y, b.z, b.w};
        unsigned short hs[8], ls[8];
#pragma unroll
        for (int j = 0; j < 8; j++) {
            hs[j] = f2bf(x[j]);
            ls[j] = f2bf(x[j] - bfu2f(hs[j]));
        }
        uint4 H = make_uint4(hs[0] | (hs[1] << 16), hs[2] | (hs[3] << 16),
                             hs[4] | (hs[5] << 16), hs[6] | (hs[7] << 16));
        uint4 L = make_uint4(ls[0] | (ls[1] << 16), ls[2] | (ls[3] << 16),
                             ls[4] | (ls[5] << 16), ls[6] | (ls[7] << 16));
        *(uint4*)(g_Bh + (size_t)t * 8) = H;
        *(uint4*)(g_Bl + (size_t)t * 8) = L;
    }
}

// ---------------- bf16-split node features ----------------
__global__ void k_prep_h(const float* __restrict__ h, int N) {
    int idx = blockIdx.x * blockDim.x + threadIdx.x;   // chunk of 8 floats
    if (idx >= N * 16) return;
    const float* src = h + (size_t)idx * 8;
    float4 a = *(const float4*)src;
    float4 b = *(const float4*)(src + 4);
    float x[8] = {a.x, a.y, a.z, a.w, b.x, b.y, b.z, b.w};
    unsigned short hs[8], ls[8];
#pragma unroll
    for (int j = 0; j < 8; j++) {
        hs[j] = f2bf(x[j]);
        ls[j] = f2bf(x[j] - bfu2f(hs[j]));
    }
    uint4 H = make_uint4(hs[0] | (hs[1] << 16), hs[2] | (hs[3] << 16),
                         hs[4] | (hs[5] << 16), hs[6] | (hs[7] << 16));
    uint4 L = make_uint4(ls[0] | (ls[1] << 16), ls[2] | (ls[3] << 16),
                         ls[4] | (ls[5] << 16), ls[6] | (ls[7] << 16));
    *(uint4*)(g_Ah + (size_t)idx * 8) = H;
    *(uint4*)(g_Al + (size_t)idx * 8) = L;
}

// ---------------- per-(dst, relation) degree counting ----------------
__global__ void k_count(const void* ei, const void* et, int E) {
    int e = blockIdx.x * blockDim.x + threadIdx.x;
    if (e >= E) return;
    int dst = edge_val(ei, E + e);
    int r   = edge_val(et, e);
    atomicAdd(&g_deg[dst * NREL + r], 1);
}

// ---------------- mma.sync GEMM: [M,128] x [128,1152], 3-term bf16 split ----------------
// CTA = 128 threads (4 warps, 2m x 2n), M-tile 64 rows (A resident, 32KB),
// N streamed in 18 stages of 64 cols, B double-buffered (2 x 32KB).
// smem total 96KB -> 2 CTAs/SM so one CTA's epilogue overlaps the other's MMA.
#define SMEM_TOTAL 98304
#define NSTAGES 18

__global__ void __launch_bounds__(128, 2) k_gemm(const float* __restrict__ bself, int M) {
    extern __shared__ char smem[];
    uint32_t sb = smem_u32(smem);
    int tid = threadIdx.x, wid = tid >> 5, lane = tid & 31;
    int bx = blockIdx.x;
    int wm = wid >> 1, wn = wid & 1;
    int g = lane >> 2, tig = lane & 3;

    // ---- A tiles (both halves), rows clamped ----
#pragma unroll
    for (int hf = 0; hf < 2; hf++) {
        const __nv_bfloat16* gsrc = hf ? g_Al : g_Ah;
#pragma unroll
        for (int i = 0; i < 8; i++) {
            int id = i * 128 + tid;
            int r = id >> 4, c8 = id & 15;
            int grow = bx * 64 + r;
            if (grow >= M) grow = M - 1;
            const void* src = gsrc + (size_t)grow * 128 + c8 * 8;
            uint32_t dst = sb + hf * 16384 + r * 256 + ((c8 ^ (r & 7)) << 4);
            CP16(dst, src);
        }
    }
    // ---- B stage loader: stage bn covers out-cols [bn*64, bn*64+64) ----
    auto cpB = [&](int bn, int s) {
#pragma unroll
        for (int hf = 0; hf < 2; hf++) {
            const __nv_bfloat16* gsrc = hf ? g_Bl : g_Bh;
#pragma unroll
            for (int i = 0; i < 8; i++) {
                int id = i * 128 + tid;
                int j = id >> 4, c8 = id & 15;
                const void* src = gsrc + (size_t)(bn * 64 + j) * 128 + c8 * 8;
                uint32_t dst = sb + 32768 + s * 32768 + hf * 16384 + j * 256 + ((c8 ^ (j & 7)) << 4);
                CP16(dst, src);
            }
        }
    };
    cpB(0, 0);
    CP_COMMIT();           // G0: A + B0
    cpB(1, 1);
    CP_COMMIT();           // G1: B1

    for (int bn = 0; bn < NSTAGES; bn++) {
        if (bn == NSTAGES - 1) asm volatile("cp.async.wait_group 0;");
        else                   asm volatile("cp.async.wait_group 1;");
        __syncthreads();

        uint32_t aBase = sb;
        uint32_t bBase = sb + 32768 + (bn & 1) * 32768;

        float acc[2][4][4];
#pragma unroll
        for (int mf = 0; mf < 2; mf++)
#pragma unroll
            for (int nb = 0; nb < 4; nb++)
#pragma unroll
                for (int q = 0; q < 4; q++) acc[mf][nb][q] = 0.f;

#pragma unroll
        for (int ks = 0; ks < 8; ks++) {
            uint32_t ah[2][4], al[2][4], bh[4][2], bl[4][2];
#pragma unroll
            for (int mf = 0; mf < 2; mf++) {
                int row = wm * 32 + mf * 16 + (lane & 15);
                int c8 = ks * 2 + (lane >> 4);
                uint32_t ad = aBase + row * 256 + ((c8 ^ (row & 7)) << 4);
                ldsm4(ah[mf], ad);
                ldsm4(al[mf], ad + 16384);
            }
#pragma unroll
            for (int p = 0; p < 2; p++) {
                int j = wn * 32 + p * 16 + (lane >> 4) * 8 + (lane & 7);
                int c8 = ks * 2 + ((lane >> 3) & 1);
                uint32_t bd = bBase + j * 256 + ((c8 ^ (j & 7)) << 4);
                uint32_t t[4];
                ldsm4(t, bd);
                bh[2 * p][0] = t[0]; bh[2 * p][1] = t[1];
                bh[2 * p + 1][0] = t[2]; bh[2 * p + 1][1] = t[3];
                ldsm4(t, bd + 16384);
                bl[2 * p][0] = t[0]; bl[2 * p][1] = t[1];
                bl[2 * p + 1][0] = t[2]; bl[2 * p + 1][1] = t[3];
            }
#pragma unroll
            for (int mf = 0; mf < 2; mf++)
#pragma unroll
                for (int nb = 0; nb < 4; nb++) {
                    mma16816(acc[mf][nb], ah[mf], bh[nb]);
                    mma16816(acc[mf][nb], ah[mf], bl[nb]);
                    mma16816(acc[mf][nb], al[mf], bh[nb]);
                }
        }

        __syncthreads();                 // all warps done reading buffer (bn&1)
        if (bn < NSTAGES - 2) {
            cpB(bn + 2, bn & 1);         // prefetch into just-freed buffer
            CP_COMMIT();
        }

        // ---- epilogue: stages 0,1 -> g_out (+bias); stages 2.. -> g_T ----
        int cn = wn * 32;
#pragma unroll
        for (int mf = 0; mf < 2; mf++) {
            int row0 = bx * 64 + wm * 32 + mf * 16 + g;
#pragma unroll
            for (int half = 0; half < 2; half++) {
                int row = row0 + half * 8;
                if (row < M) {
                    if (bn < 2) {
                        float* o = g_out + (size_t)row * HIDDEN + bn * 64 + cn;
                        const float* bs = bself + bn * 64 + cn;
#pragma unroll
                        for (int nb = 0; nb < 4; nb++) {
                            int col = nb * 8 + tig * 2;
                            float2 v;
                            v.x = acc[mf][nb][half * 2 + 0] + __ldg(bs + col);
                            v.y = acc[mf][nb][half * 2 + 1] + __ldg(bs + col + 1);
                            *(float2*)(o + col) = v;
                        }
                    } else {
                        float* o = g_T + (size_t)row * 1024 + (bn - 2) * 64 + cn;
#pragma unroll
                        for (int nb = 0; nb < 4; nb++) {
                            int col = nb * 8 + tig * 2;
                            float2 v;
                            v.x = acc[mf][nb][half * 2 + 0];
                            v.y = acc[mf][nb][half * 2 + 1];
                            *(float2*)(o + col) = v;
                        }
                    }
                }
            }
        }
    }
}

// ---------------- edge scatter: out[dst] += T[src, r] / deg ----------------
__global__ void k_scatter(const void* ei, const void* et, int E) {
    int gwarp = (blockIdx.x * blockDim.x + threadIdx.x) >> 5;
    int lane = threadIdx.x & 31;
    if (gwarp >= E) return;
    int e = gwarp;
    int src = edge_val(ei, e);
    int dst = edge_val(ei, E + e);
    int r   = edge_val(et, e);
    int deg = g_deg[dst * NREL + r];
    float inv = 1.0f / (float)deg;
    float4 v = *(const float4*)&g_T[(size_t)src * 1024 + r * HIDDEN + lane * 4];
    v.x *= inv; v.y *= inv; v.z *= inv; v.w *= inv;
    atomicAdd((float4*)&g_out[(size_t)dst * HIDDEN + lane * 4], v);
}

// ---------------- ReLU + LayerNorm ----------------
__global__ void k_ln(const float* __restrict__ gamma, const float* __restrict__ beta,
                     float* __restrict__ out, int N) {
    int gwarp = (blockIdx.x * blockDim.x + threadIdx.x) >> 5;
    int lane = threadIdx.x & 31;
    if (gwarp >= N) return;
    float4 v = *(const float4*)&g_out[(size_t)gwarp * HIDDEN + lane * 4];
    v.x = fmaxf(v.x, 0.f); v.y = fmaxf(v.y, 0.f);
    v.z = fmaxf(v.z, 0.f); v.w = fmaxf(v.w, 0.f);
    float s = v.x + v.y + v.z + v.w;
#pragma unroll
    for (int o = 16; o > 0; o >>= 1) s += __shfl_xor_sync(0xffffffffu, s, o);
    float mu = s * (1.0f / HIDDEN);
    float dx = v.x - mu, dy = v.y - mu, dz = v.z - mu, dw = v.w - mu;
    float ss = dx * dx + dy * dy + dz * dz + dw * dw;
#pragma unroll
    for (int o = 16; o > 0; o >>= 1) ss += __shfl_xor_sync(0xffffffffu, ss, o);
    float rs = rsqrtf(ss * (1.0f / HIDDEN) + 1e-5f);
    float4 gg = *(const float4*)&gamma[lane * 4];
    float4 bb = *(const float4*)&beta[lane * 4];
    float4 y = make_float4(dx * rs * gg.x + bb.x, dy * rs * gg.y + bb.y,
                           dz * rs * gg.z + bb.z, dw * rs * gg.w + bb.w);
    *(float4*)&out[(size_t)gwarp * HIDDEN + lane * 4] = y;
}

// ---------------- launch ----------------
extern "C" void kernel_launch(void* const* d_in, const int* in_sizes, int n_in,
                              void* d_out, int out_size) {
    const float* h     = (const float*)d_in[0];
    const void*  ei    = d_in[1];
    const void*  et    = d_in[2];
    const float* Wself = (const float*)d_in[3];
    const float* bself = (const float*)d_in[4];
    const float* Wrel  = (const float*)d_in[5];
    const float* gamma = (const float*)d_in[6];
    const float* beta  = (const float*)d_in[7];
    float* out = (float*)d_out;

    int N = in_sizes[0] / HIDDEN;
    int E = in_sizes[2];

    cudaFuncSetAttribute(k_gemm, cudaFuncAttributeMaxDynamicSharedMemorySize, SMEM_TOTAL);

    k_detect<<<1, 1>>>(ei);
    k_init<<<256, 256>>>(Wself, Wrel, N);
    k_prep_h<<<(N * 16 + 255) / 256, 256>>>(h, N);
    k_count<<<(E + 255) / 256, 256>>>(ei, et, E);

    int mblocks = (N + 63) / 64;
    k_gemm<<<mblocks, 128, SMEM_TOTAL>>>(bself, N);

    int sblocks = (E * 32 + 255) / 256;
    k_scatter<<<sblocks, 256>>>(ei, et, E);

    int lblocks = (N * 32 + 255) / 256;
    k_ln<<<lblocks, 256>>>(gamma, beta, out, N);
}

// round 5
// speedup vs baseline: 2.2255x; 1.0538x over previous
#include <cuda_runtime.h>
#include <cuda_bf16.h>
#include <cuda_fp16.h>
#include <cstdint>

#define HIDDEN 128
#define NREL   8
#define MAXN   100000

// ---------------- device scratch ----------------
__device__ int   g_is64;
__device__ int   g_deg[MAXN * NREL];
__device__ __align__(16) __half g_T[(size_t)MAXN * 1024];     // relation-transformed feats (fp16)
__device__ __align__(16) float g_out[(size_t)MAXN * HIDDEN];  // pre-activation accumulator
__device__ __align__(16) __nv_bfloat16 g_Bh[1152 * HIDDEN];   // [out_col][k]
__device__ __align__(16) __nv_bfloat16 g_Bl[1152 * HIDDEN];

// ---------------- helpers ----------------
__device__ __forceinline__ uint32_t smem_u32(const void* p) {
    uint32_t a;
    asm("{ .reg .u64 t; cvta.to.shared.u64 t, %1; cvt.u32.u64 %0, t; }" : "=r"(a) : "l"(p));
    return a;
}
__device__ __forceinline__ void ldsm4(uint32_t* r, uint32_t addr) {
    asm volatile("ldmatrix.sync.aligned.m8n8.x4.shared.b16 {%0,%1,%2,%3}, [%4];"
                 : "=r"(r[0]), "=r"(r[1]), "=r"(r[2]), "=r"(r[3]) : "r"(addr));
}
__device__ __forceinline__ void mma16816(float* d, const uint32_t* a, const uint32_t* b) {
    asm volatile("mma.sync.aligned.m16n8k16.row.col.f32.bf16.bf16.f32 "
                 "{%0,%1,%2,%3}, {%4,%5,%6,%7}, {%8,%9}, {%0,%1,%2,%3};"
                 : "+f"(d[0]), "+f"(d[1]), "+f"(d[2]), "+f"(d[3])
                 : "r"(a[0]), "r"(a[1]), "r"(a[2]), "r"(a[3]), "r"(b[0]), "r"(b[1]));
}
#define CP16(dst, src) asm volatile("cp.async.cg.shared.global [%0], [%1], 16;" :: "r"(dst), "l"(src))
#define CP_COMMIT()    asm volatile("cp.async.commit_group;")

static __device__ __forceinline__ unsigned short f2bf(float f) {
    __nv_bfloat16 b = __float2bfloat16(f);
    return *reinterpret_cast<unsigned short*>(&b);
}
static __device__ __forceinline__ float bfu2f(unsigned short u) {
    __nv_bfloat16 b;
    *reinterpret_cast<unsigned short*>(&b) = u;
    return __bfloat162float(b);
}

// ---------------- edge dtype detect ----------------
__global__ void k_detect(const void* ei) {
    const long long* p = (const long long*)ei;
    int ok64 = 1;
    for (int i = 0; i < 16; i++) {
        long long v = p[i];
        if (v < 0 || v >= (1LL << 31)) ok64 = 0;
    }
    g_is64 = ok64;
}
__device__ __forceinline__ int edge_val(const void* arr, int idx, int is64) {
    if (is64) return (int)((const long long*)arr)[idx];
    return ((const int*)arr)[idx];
}

// ---------------- init: zero deg + bf16-split weights ----------------
__global__ void k_init(const float* __restrict__ Wself, const float* __restrict__ Wrel, int N) {
    int stride = gridDim.x * blockDim.x;
    int i0 = blockIdx.x * blockDim.x + threadIdx.x;
    int nd = N * NREL;
    for (int t = i0; t < nd; t += stride) g_deg[t] = 0;
    for (int t = i0; t < 18432; t += stride) {   // 1152*128/8 chunks of 8 floats
        const float* src = (t < 2048) ? (Wself + (size_t)t * 8) : (Wrel + (size_t)(t - 2048) * 8);
        float4 a = *(const float4*)src;
        float4 b = *(const float4*)(src + 4);
        float x[8] = {a.x, a.y, a.z, a.w, b.x, b.y, b.z, b.w};
        unsigned short hs[8], ls[8];
#pragma unroll
        for (int j = 0; j < 8; j++) {
            hs[j] = f2bf(x[j]);
            ls[j] = f2bf(x[j] - bfu2f(hs[j]));
        }
        uint4 H = make_uint4(hs[0] | (hs[1] << 16), hs[2] | (hs[3] << 16),
                             hs[4] | (hs[5] << 16), hs[6] | (hs[7] << 16));
        uint4 L = make_uint4(ls[0] | (ls[1] << 16), ls[2] | (ls[3] << 16),
                             ls[4] | (ls[5] << 16), ls[6] | (ls[7] << 16));
        *(uint4*)(g_Bh + (size_t)t * 8) = H;
        *(uint4*)(g_Bl + (size_t)t * 8) = L;
    }
}

// ---------------- per-(dst, relation) degree counting (4 edges/thread) ----------------
__global__ void k_count(const void* ei, const void* et, int E) {
    int is64 = g_is64;
    int base = (blockIdx.x * blockDim.x + threadIdx.x) * 4;
#pragma unroll
    for (int j = 0; j < 4; j++) {
        int e = base + j;
        if (e < E) {
            int dst = edge_val(ei, E + e, is64);
            int r   = edge_val(et, e, is64);
            atomicAdd(&g_deg[dst * NREL + r], 1);
        }
    }
}

// ---------------- mma.sync GEMM: [M,128] x [128,1152], 3-term bf16 split ----------------
// CTA = 128 threads (4 warps, 2m x 2n), M-tile 64 rows. A loaded fp32 from h and
// split to bf16 hi/lo in-kernel (prep fused). N streamed in 18 stages of 64 cols,
// B double-buffered. smem 96KB -> 2 CTAs/SM.
#define SMEM_TOTAL 98304
#define NSTAGES 18

__global__ void __launch_bounds__(128, 2) k_gemm(const float* __restrict__ h,
                                                 const float* __restrict__ bself, int M) {
    extern __shared__ char smem[];
    uint32_t sb = smem_u32(smem);
    int tid = threadIdx.x, wid = tid >> 5, lane = tid & 31;
    int bx = blockIdx.x;
    int wm = wid >> 1, wn = wid & 1;
    int g = lane >> 2, tig = lane & 3;

    // ---- B stage loader: stage bn covers out-cols [bn*64, bn*64+64) ----
    auto cpB = [&](int bn, int s) {
#pragma unroll
        for (int hf = 0; hf < 2; hf++) {
            const __nv_bfloat16* gsrc = hf ? g_Bl : g_Bh;
#pragma unroll
            for (int i = 0; i < 8; i++) {
                int id = i * 128 + tid;
                int j = id >> 4, c8 = id & 15;
                const void* src = gsrc + (size_t)(bn * 64 + j) * 128 + c8 * 8;
                uint32_t dst = sb + 32768 + s * 32768 + hf * 16384 + j * 256 + ((c8 ^ (j & 7)) << 4);
                CP16(dst, src);
            }
        }
    };
    cpB(0, 0);
    CP_COMMIT();           // G0: B0
    cpB(1, 1);
    CP_COMMIT();           // G1: B1

    // ---- A: load fp32 rows, split to bf16 hi/lo, store swizzled to smem ----
#pragma unroll
    for (int i = 0; i < 16; i++) {
        int id = i * 128 + tid;
        int r = id >> 5, c4 = id & 31;          // 64 rows x 32 float4-chunks
        int grow = bx * 64 + r;
        if (grow >= M) grow = M - 1;
        float4 v = *(const float4*)(h + (size_t)grow * HIDDEN + c4 * 4);
        float x[4] = {v.x, v.y, v.z, v.w};
        unsigned short hs[4], ls[4];
#pragma unroll
        for (int j = 0; j < 4; j++) {
            hs[j] = f2bf(x[j]);
            ls[j] = f2bf(x[j] - bfu2f(hs[j]));
        }
        uint2 H = make_uint2(hs[0] | (hs[1] << 16), hs[2] | (hs[3] << 16));
        uint2 L = make_uint2(ls[0] | (ls[1] << 16), ls[2] | (ls[3] << 16));
        int c8 = c4 >> 1;
        uint32_t off = r * 256 + ((c8 ^ (r & 7)) << 4) + ((c4 & 1) << 3);
        *(uint2*)(smem + off) = H;
        *(uint2*)(smem + 16384 + off) = L;
    }

    for (int bn = 0; bn < NSTAGES; bn++) {
        if (bn == NSTAGES - 1) asm volatile("cp.async.wait_group 0;");
        else                   asm volatile("cp.async.wait_group 1;");
        __syncthreads();

        uint32_t aBase = sb;
        uint32_t bBase = sb + 32768 + (bn & 1) * 32768;

        float acc[2][4][4];
#pragma unroll
        for (int mf = 0; mf < 2; mf++)
#pragma unroll
            for (int nb = 0; nb < 4; nb++)
#pragma unroll
                for (int q = 0; q < 4; q++) acc[mf][nb][q] = 0.f;

#pragma unroll
        for (int ks = 0; ks < 8; ks++) {
            uint32_t ah[2][4], al[2][4], bh[4][2], bl[4][2];
#pragma unroll
            for (int mf = 0; mf < 2; mf++) {
                int row = wm * 32 + mf * 16 + (lane & 15);
                int c8 = ks * 2 + (lane >> 4);
                uint32_t ad = aBase + row * 256 + ((c8 ^ (row & 7)) << 4);
                ldsm4(ah[mf], ad);
                ldsm4(al[mf], ad + 16384);
            }
#pragma unroll
            for (int p = 0; p < 2; p++) {
                int j = wn * 32 + p * 16 + (lane >> 4) * 8 + (lane & 7);
                int c8 = ks * 2 + ((lane >> 3) & 1);
                uint32_t bd = bBase + j * 256 + ((c8 ^ (j & 7)) << 4);
                uint32_t t[4];
                ldsm4(t, bd);
                bh[2 * p][0] = t[0]; bh[2 * p][1] = t[1];
                bh[2 * p + 1][0] = t[2]; bh[2 * p + 1][1] = t[3];
                ldsm4(t, bd + 16384);
                bl[2 * p][0] = t[0]; bl[2 * p][1] = t[1];
                bl[2 * p + 1][0] = t[2]; bl[2 * p + 1][1] = t[3];
            }
#pragma unroll
            for (int mf = 0; mf < 2; mf++)
#pragma unroll
                for (int nb = 0; nb < 4; nb++) {
                    mma16816(acc[mf][nb], ah[mf], bh[nb]);
                    mma16816(acc[mf][nb], ah[mf], bl[nb]);
                    mma16816(acc[mf][nb], al[mf], bh[nb]);
                }
        }

        __syncthreads();                 // all warps done reading buffer (bn&1)
        if (bn < NSTAGES - 2) {
            cpB(bn + 2, bn & 1);         // prefetch into just-freed buffer
            CP_COMMIT();
        }

        // ---- epilogue: stages 0,1 -> g_out fp32 (+bias); stages 2.. -> g_T fp16 ----
        int cn = wn * 32;
#pragma unroll
        for (int mf = 0; mf < 2; mf++) {
            int row0 = bx * 64 + wm * 32 + mf * 16 + g;
#pragma unroll
            for (int half = 0; half < 2; half++) {
                int row = row0 + half * 8;
                if (row < M) {
                    if (bn < 2) {
                        float* o = g_out + (size_t)row * HIDDEN + bn * 64 + cn;
                        const float* bs = bself + bn * 64 + cn;
#pragma unroll
                        for (int nb = 0; nb < 4; nb++) {
                            int col = nb * 8 + tig * 2;
                            float2 v;
                            v.x = acc[mf][nb][half * 2 + 0] + __ldg(bs + col);
                            v.y = acc[mf][nb][half * 2 + 1] + __ldg(bs + col + 1);
                            *(float2*)(o + col) = v;
                        }
                    } else {
                        __half* o = g_T + (size_t)row * 1024 + (bn - 2) * 64 + cn;
#pragma unroll
                        for (int nb = 0; nb < 4; nb++) {
                            int col = nb * 8 + tig * 2;
                            __half2 p = __floats2half2_rn(acc[mf][nb][half * 2 + 0],
                                                          acc[mf][nb][half * 2 + 1]);
                            *(uint32_t*)(o + col) = *(uint32_t*)&p;
                        }
                    }
                }
            }
        }
    }
}

// ---------------- edge scatter: out[dst] += T[src, r] / deg (fp16 gather) ----------------
__global__ void k_scatter(const void* ei, const void* et, int E) {
    int is64 = g_is64;
    int gwarp = (blockIdx.x * blockDim.x + threadIdx.x) >> 5;
    int lane = threadIdx.x & 31;
    if (gwarp >= E) return;
    int e = gwarp;
    int src = edge_val(ei, e, is64);
    int dst = edge_val(ei, E + e, is64);
    int r   = edge_val(et, e, is64);
    int deg = g_deg[dst * NREL + r];
    float inv = 1.0f / (float)deg;
    const __half* tp = g_T + (size_t)src * 1024 + r * HIDDEN + lane * 4;
    uint2 hv = *(const uint2*)tp;
    __half2 a = *(__half2*)&hv.x;
    __half2 b = *(__half2*)&hv.y;
    float2 fa = __half22float2(a);
    float2 fb = __half22float2(b);
    float4 v = make_float4(fa.x * inv, fa.y * inv, fb.x * inv, fb.y * inv);
    atomicAdd((float4*)&g_out[(size_t)dst * HIDDEN + lane * 4], v);
}

// ---------------- ReLU + LayerNorm ----------------
__global__ void k_ln(const float* __restrict__ gamma, const float* __restrict__ beta,
                     float* __restrict__ out, int N) {
    int gwarp = (blockIdx.x * blockDim.x + threadIdx.x) >> 5;
    int lane = threadIdx.x & 31;
    if (gwarp >= N) return;
    float4 v = *(const float4*)&g_out[(size_t)gwarp * HIDDEN + lane * 4];
    v.x = fmaxf(v.x, 0.f); v.y = fmaxf(v.y, 0.f);
    v.z = fmaxf(v.z, 0.f); v.w = fmaxf(v.w, 0.f);
    float s = v.x + v.y + v.z + v.w;
#pragma unroll
    for (int o = 16; o > 0; o >>= 1) s += __shfl_xor_sync(0xffffffffu, s, o);
    float mu = s * (1.0f / HIDDEN);
    float dx = v.x - mu, dy = v.y - mu, dz = v.z - mu, dw = v.w - mu;
    float ss = dx * dx + dy * dy + dz * dz + dw * dw;
#pragma unroll
    for (int o = 16; o > 0; o >>= 1) ss += __shfl_xor_sync(0xffffffffu, ss, o);
    float rs = rsqrtf(ss * (1.0f / HIDDEN) + 1e-5f);
    float4 gg = *(const float4*)&gamma[lane * 4];
    float4 bb = *(const float4*)&beta[lane * 4];
    float4 y = make_float4(dx * rs * gg.x + bb.x, dy * rs * gg.y + bb.y,
                           dz * rs * gg.z + bb.z, dw * rs * gg.w + bb.w);
    *(float4*)&out[(size_t)gwarp * HIDDEN + lane * 4] = y;
}

// ---------------- launch ----------------
extern "C" void kernel_launch(void* const* d_in, const int* in_sizes, int n_in,
                              void* d_out, int out_size) {
    const float* h     = (const float*)d_in[0];
    const void*  ei    = d_in[1];
    const void*  et    = d_in[2];
    const float* Wself = (const float*)d_in[3];
    const float* bself = (const float*)d_in[4];
    const float* Wrel  = (const float*)d_in[5];
    const float* gamma = (const float*)d_in[6];
    const float* beta  = (const float*)d_in[7];
    float* out = (float*)d_out;

    int N = in_sizes[0] / HIDDEN;
    int E = in_sizes[2];

    cudaFuncSetAttribute(k_gemm, cudaFuncAttributeMaxDynamicSharedMemorySize, SMEM_TOTAL);

    k_detect<<<1, 1>>>(ei);
    k_init<<<256, 256>>>(Wself, Wrel, N);
    k_count<<<(E + 1023) / 1024, 256>>>(ei, et, E);

    int mblocks = (N + 63) / 64;
    k_gemm<<<mblocks, 128, SMEM_TOTAL>>>(h, bself, N);

    int sblocks = (E * 32 + 255) / 256;
    k_scatter<<<sblocks, 256>>>(ei, et, E);

    int lblocks = (N * 32 + 255) / 256;
    k_ln<<<lblocks, 256>>>(gamma, beta, out, N);
}

// round 6
// speedup vs baseline: 2.9417x; 1.3218x over previous
#include <cuda_runtime.h>
#include <cuda_bf16.h>
#include <cuda_fp16.h>
#include <cstdint>

#define HIDDEN 128
#define NREL   8
#define MAXN   100000

// ---------------- device scratch ----------------
__device__ int   g_is64;
__device__ int   g_deg[MAXN * NREL];
__device__ __align__(16) __half g_T[(size_t)MAXN * 1024];     // relation messages (fp16)
__device__ __align__(16) float g_out[(size_t)MAXN * HIDDEN];  // pre-activation accumulator
__device__ __align__(16) __nv_bfloat16 g_Bh[128 * HIDDEN];    // W_self bf16 hi  [col][k]
__device__ __align__(16) __nv_bfloat16 g_Bl[128 * HIDDEN];    // W_self bf16 lo
__device__ __align__(16) __half g_Bf[1024 * HIDDEN];          // W_rel fp16      [col][k]

// ---------------- helpers ----------------
__device__ __forceinline__ uint32_t smem_u32(const void* p) {
    uint32_t a;
    asm("{ .reg .u64 t; cvta.to.shared.u64 t, %1; cvt.u32.u64 %0, t; }" : "=r"(a) : "l"(p));
    return a;
}
__device__ __forceinline__ void ldsm4(uint32_t* r, uint32_t addr) {
    asm volatile("ldmatrix.sync.aligned.m8n8.x4.shared.b16 {%0,%1,%2,%3}, [%4];"
                 : "=r"(r[0]), "=r"(r[1]), "=r"(r[2]), "=r"(r[3]) : "r"(addr));
}
__device__ __forceinline__ void mma_bf16(float* d, const uint32_t* a, const uint32_t* b) {
    asm volatile("mma.sync.aligned.m16n8k16.row.col.f32.bf16.bf16.f32 "
                 "{%0,%1,%2,%3}, {%4,%5,%6,%7}, {%8,%9}, {%0,%1,%2,%3};"
                 : "+f"(d[0]), "+f"(d[1]), "+f"(d[2]), "+f"(d[3])
                 : "r"(a[0]), "r"(a[1]), "r"(a[2]), "r"(a[3]), "r"(b[0]), "r"(b[1]));
}
__device__ __forceinline__ void mma_f16(float* d, const uint32_t* a, const uint32_t* b) {
    asm volatile("mma.sync.aligned.m16n8k16.row.col.f32.f16.f16.f32 "
                 "{%0,%1,%2,%3}, {%4,%5,%6,%7}, {%8,%9}, {%0,%1,%2,%3};"
                 : "+f"(d[0]), "+f"(d[1]), "+f"(d[2]), "+f"(d[3])
                 : "r"(a[0]), "r"(a[1]), "r"(a[2]), "r"(a[3]), "r"(b[0]), "r"(b[1]));
}
#define CP16(dst, src) asm volatile("cp.async.cg.shared.global [%0], [%1], 16;" :: "r"(dst), "l"(src))
#define CP_COMMIT()    asm volatile("cp.async.commit_group;")

static __device__ __forceinline__ unsigned short f2bf(float f) {
    __nv_bfloat16 b = __float2bfloat16(f);
    return *reinterpret_cast<unsigned short*>(&b);
}
static __device__ __forceinline__ float bfu2f(unsigned short u) {
    __nv_bfloat16 b;
    *reinterpret_cast<unsigned short*>(&b) = u;
    return __bfloat162float(b);
}

// ---------------- edge dtype detect ----------------
__global__ void k_detect(const void* ei) {
    const long long* p = (const long long*)ei;
    int ok64 = 1;
    for (int i = 0; i < 16; i++) {
        long long v = p[i];
        if (v < 0 || v >= (1LL << 31)) ok64 = 0;
    }
    g_is64 = ok64;
}
__device__ __forceinline__ int edge_val(const void* arr, int idx, int is64) {
    if (is64) return (int)((const long long*)arr)[idx];
    return ((const int*)arr)[idx];
}

// ---------------- init: zero deg + weight conversions ----------------
__global__ void k_init(const float* __restrict__ Wself, const float* __restrict__ Wrel, int N) {
    int stride = gridDim.x * blockDim.x;
    int i0 = blockIdx.x * blockDim.x + threadIdx.x;
    int nd = N * NREL;
    for (int t = i0; t < nd; t += stride) g_deg[t] = 0;
    // W_self: bf16 hi/lo split, 128*128/8 = 2048 chunks
    for (int t = i0; t < 2048; t += stride) {
        const float* src = Wself + (size_t)t * 8;
        float4 a = *(const float4*)src;
        float4 b = *(const float4*)(src + 4);
        float x[8] = {a.x, a.y, a.z, a.w, b.x, b.y, b.z, b.w};
        unsigned short hs[8], ls[8];
#pragma unroll
        for (int j = 0; j < 8; j++) {
            hs[j] = f2bf(x[j]);
            ls[j] = f2bf(x[j] - bfu2f(hs[j]));
        }
        uint4 H = make_uint4(hs[0] | (hs[1] << 16), hs[2] | (hs[3] << 16),
                             hs[4] | (hs[5] << 16), hs[6] | (hs[7] << 16));
        uint4 L = make_uint4(ls[0] | (ls[1] << 16), ls[2] | (ls[3] << 16),
                             ls[4] | (ls[5] << 16), ls[6] | (ls[7] << 16));
        *(uint4*)(g_Bh + (size_t)t * 8) = H;
        *(uint4*)(g_Bl + (size_t)t * 8) = L;
    }
    // W_rel: fp16, 1024*128/8 = 16384 chunks
    for (int t = i0; t < 16384; t += stride) {
        const float* src = Wrel + (size_t)t * 8;
        float4 a = *(const float4*)src;
        float4 b = *(const float4*)(src + 4);
        __half2 h0 = __floats2half2_rn(a.x, a.y);
        __half2 h1 = __floats2half2_rn(a.z, a.w);
        __half2 h2 = __floats2half2_rn(b.x, b.y);
        __half2 h3 = __floats2half2_rn(b.z, b.w);
        uint4 V = make_uint4(*(uint32_t*)&h0, *(uint32_t*)&h1, *(uint32_t*)&h2, *(uint32_t*)&h3);
        *(uint4*)(g_Bf + (size_t)t * 8) = V;
    }
}

// ---------------- per-(dst, relation) degree counting ----------------
__global__ void k_count(const void* ei, const void* et, int E) {
    int is64 = g_is64;
    int base = (blockIdx.x * blockDim.x + threadIdx.x) * 4;
#pragma unroll
    for (int j = 0; j < 4; j++) {
        int e = base + j;
        if (e < E) {
            int dst = edge_val(ei, E + e, is64);
            int r   = edge_val(et, e, is64);
            atomicAdd(&g_deg[dst * NREL + r], 1);
        }
    }
}

// ================= relation GEMM: [M,128] x [128,1024] fp16 single-term =================
// 128 threads (2m x 2n warps), M-tile 64, A fp16 resident (16KB), B dbl-buffered 16KB stages.
// smem 48KB -> 4 CTAs/SM.
#define REL_SMEM 49152
#define REL_STAGES 16

__global__ void __launch_bounds__(128, 4) k_gemm_rel(const float* __restrict__ h, int M) {
    extern __shared__ char smem[];
    uint32_t sb = smem_u32(smem);
    int tid = threadIdx.x, wid = tid >> 5, lane = tid & 31;
    int bx = blockIdx.x;
    int wm = wid >> 1, wn = wid & 1;
    int g = lane >> 2, tig = lane & 3;

    auto cpB = [&](int bn, int s) {
#pragma unroll
        for (int i = 0; i < 8; i++) {
            int id = i * 128 + tid;
            int j = id >> 4, c8 = id & 15;
            const void* src = g_Bf + (size_t)(bn * 64 + j) * 128 + c8 * 8;
            uint32_t dst = sb + 16384 + s * 16384 + j * 256 + ((c8 ^ (j & 7)) << 4);
            CP16(dst, src);
        }
    };
    cpB(0, 0); CP_COMMIT();
    cpB(1, 1); CP_COMMIT();

    // A: fp32 -> fp16 -> swizzled smem
#pragma unroll
    for (int i = 0; i < 16; i++) {
        int id = i * 128 + tid;
        int r = id >> 5, c4 = id & 31;
        int grow = bx * 64 + r;
        if (grow >= M) grow = M - 1;
        float4 v = *(const float4*)(h + (size_t)grow * HIDDEN + c4 * 4);
        __half2 p0 = __floats2half2_rn(v.x, v.y);
        __half2 p1 = __floats2half2_rn(v.z, v.w);
        uint2 V = make_uint2(*(uint32_t*)&p0, *(uint32_t*)&p1);
        int c8 = c4 >> 1;
        uint32_t off = r * 256 + ((c8 ^ (r & 7)) << 4) + ((c4 & 1) << 3);
        *(uint2*)(smem + off) = V;
    }

    for (int bn = 0; bn < REL_STAGES; bn++) {
        if (bn == REL_STAGES - 1) asm volatile("cp.async.wait_group 0;");
        else                      asm volatile("cp.async.wait_group 1;");
        __syncthreads();

        uint32_t bBase = sb + 16384 + (bn & 1) * 16384;
        float acc[2][4][4];
#pragma unroll
        for (int mf = 0; mf < 2; mf++)
#pragma unroll
            for (int nb = 0; nb < 4; nb++)
#pragma unroll
                for (int q = 0; q < 4; q++) acc[mf][nb][q] = 0.f;

#pragma unroll
        for (int ks = 0; ks < 8; ks++) {
            uint32_t af[2][4], bf[4][2];
#pragma unroll
            for (int mf = 0; mf < 2; mf++) {
                int row = wm * 32 + mf * 16 + (lane & 15);
                int c8 = ks * 2 + (lane >> 4);
                ldsm4(af[mf], sb + row * 256 + ((c8 ^ (row & 7)) << 4));
            }
#pragma unroll
            for (int p = 0; p < 2; p++) {
                int j = wn * 32 + p * 16 + (lane >> 4) * 8 + (lane & 7);
                int c8 = ks * 2 + ((lane >> 3) & 1);
                uint32_t t[4];
                ldsm4(t, bBase + j * 256 + ((c8 ^ (j & 7)) << 4));
                bf[2 * p][0] = t[0]; bf[2 * p][1] = t[1];
                bf[2 * p + 1][0] = t[2]; bf[2 * p + 1][1] = t[3];
            }
#pragma unroll
            for (int mf = 0; mf < 2; mf++)
#pragma unroll
                for (int nb = 0; nb < 4; nb++)
                    mma_f16(acc[mf][nb], af[mf], bf[nb]);
        }

        __syncthreads();
        if (bn < REL_STAGES - 2) { cpB(bn + 2, bn & 1); CP_COMMIT(); }

        int cn = wn * 32;
#pragma unroll
        for (int mf = 0; mf < 2; mf++) {
            int row0 = bx * 64 + wm * 32 + mf * 16 + g;
#pragma unroll
            for (int half = 0; half < 2; half++) {
                int row = row0 + half * 8;
                if (row < M) {
                    __half* o = g_T + (size_t)row * 1024 + bn * 64 + cn;
#pragma unroll
                    for (int nb = 0; nb < 4; nb++) {
                        int col = nb * 8 + tig * 2;
                        __half2 p = __floats2half2_rn(acc[mf][nb][half * 2 + 0],
                                                      acc[mf][nb][half * 2 + 1]);
                        *(uint32_t*)(o + col) = *(uint32_t*)&p;
                    }
                }
            }
        }
    }
}

// ================= self GEMM: [M,128] x [128,128] 3-term bf16 split =================
// 128 threads (2m x 2n warps, warp tile 32x64), M-tile 64. A hi/lo 32KB + B hi/lo 64KB = 96KB
// -> 2 CTAs/SM. B resident (no streaming).
#define SELF_SMEM 98304

__global__ void __launch_bounds__(128, 2) k_gemm_self(const float* __restrict__ h,
                                                      const float* __restrict__ bself, int M) {
    extern __shared__ char smem[];
    uint32_t sb = smem_u32(smem);
    int tid = threadIdx.x, wid = tid >> 5, lane = tid & 31;
    int bx = blockIdx.x;
    int wm = wid >> 1, wn = wid & 1;
    int g = lane >> 2, tig = lane & 3;

    // B: 128 cols x 16 chunks, hi at 32768, lo at 65536
#pragma unroll
    for (int hf = 0; hf < 2; hf++) {
        const __nv_bfloat16* gsrc = hf ? g_Bl : g_Bh;
#pragma unroll
        for (int i = 0; i < 16; i++) {
            int id = i * 128 + tid;
            int j = id >> 4, c8 = id & 15;
            const void* src = gsrc + (size_t)j * 128 + c8 * 8;
            uint32_t dst = sb + 32768 + hf * 32768 + j * 256 + ((c8 ^ (j & 7)) << 4);
            CP16(dst, src);
        }
    }
    CP_COMMIT();

    // A: fp32 -> bf16 hi/lo -> swizzled smem (hi at 0, lo at 16384)
#pragma unroll
    for (int i = 0; i < 16; i++) {
        int id = i * 128 + tid;
        int r = id >> 5, c4 = id & 31;
        int grow = bx * 64 + r;
        if (grow >= M) grow = M - 1;
        float4 v = *(const float4*)(h + (size_t)grow * HIDDEN + c4 * 4);
        float x[4] = {v.x, v.y, v.z, v.w};
        unsigned short hs[4], ls[4];
#pragma unroll
        for (int j = 0; j < 4; j++) {
            hs[j] = f2bf(x[j]);
            ls[j] = f2bf(x[j] - bfu2f(hs[j]));
        }
        uint2 H = make_uint2(hs[0] | (hs[1] << 16), hs[2] | (hs[3] << 16));
        uint2 L = make_uint2(ls[0] | (ls[1] << 16), ls[2] | (ls[3] << 16));
        int c8 = c4 >> 1;
        uint32_t off = r * 256 + ((c8 ^ (r & 7)) << 4) + ((c4 & 1) << 3);
        *(uint2*)(smem + off) = H;
        *(uint2*)(smem + 16384 + off) = L;
    }
    asm volatile("cp.async.wait_group 0;");
    __syncthreads();

    float acc[2][8][4];
#pragma unroll
    for (int mf = 0; mf < 2; mf++)
#pragma unroll
        for (int nb = 0; nb < 8; nb++)
#pragma unroll
            for (int q = 0; q < 4; q++) acc[mf][nb][q] = 0.f;

#pragma unroll
    for (int ks = 0; ks < 8; ks++) {
        uint32_t ah[2][4], al[2][4], bh[8][2], bl[8][2];
#pragma unroll
        for (int mf = 0; mf < 2; mf++) {
            int row = wm * 32 + mf * 16 + (lane & 15);
            int c8 = ks * 2 + (lane >> 4);
            uint32_t ad = sb + row * 256 + ((c8 ^ (row & 7)) << 4);
            ldsm4(ah[mf], ad);
            ldsm4(al[mf], ad + 16384);
        }
#pragma unroll
        for (int p = 0; p < 4; p++) {
            int j = wn * 64 + p * 16 + (lane >> 4) * 8 + (lane & 7);
            int c8 = ks * 2 + ((lane >> 3) & 1);
            uint32_t bd = sb + 32768 + j * 256 + ((c8 ^ (j & 7)) << 4);
            uint32_t t[4];
            ldsm4(t, bd);
            bh[2 * p][0] = t[0]; bh[2 * p][1] = t[1];
            bh[2 * p + 1][0] = t[2]; bh[2 * p + 1][1] = t[3];
            ldsm4(t, bd + 32768);
            bl[2 * p][0] = t[0]; bl[2 * p][1] = t[1];
            bl[2 * p + 1][0] = t[2]; bl[2 * p + 1][1] = t[3];
        }
#pragma unroll
        for (int mf = 0; mf < 2; mf++)
#pragma unroll
            for (int nb = 0; nb < 8; nb++) {
                mma_bf16(acc[mf][nb], ah[mf], bh[nb]);
                mma_bf16(acc[mf][nb], ah[mf], bl[nb]);
                mma_bf16(acc[mf][nb], al[mf], bh[nb]);
            }
    }

#pragma unroll
    for (int mf = 0; mf < 2; mf++) {
        int row0 = bx * 64 + wm * 32 + mf * 16 + g;
#pragma unroll
        for (int half = 0; half < 2; half++) {
            int row = row0 + half * 8;
            if (row < M) {
                float* o = g_out + (size_t)row * HIDDEN + wn * 64;
                const float* bs = bself + wn * 64;
#pragma unroll
                for (int nb = 0; nb < 8; nb++) {
                    int col = nb * 8 + tig * 2;
                    float2 v;
                    v.x = acc[mf][nb][half * 2 + 0] + __ldg(bs + col);
                    v.y = acc[mf][nb][half * 2 + 1] + __ldg(bs + col + 1);
                    *(float2*)(o + col) = v;
                }
            }
        }
    }
}

// ---------------- edge scatter: out[dst] += T[src, r] / deg (fp16 gather) ----------------
__global__ void k_scatter(const void* ei, const void* et, int E) {
    int is64 = g_is64;
    int gwarp = (blockIdx.x * blockDim.x + threadIdx.x) >> 5;
    int lane = threadIdx.x & 31;
    if (gwarp >= E) return;
    int e = gwarp;
    int src = edge_val(ei, e, is64);
    int dst = edge_val(ei, E + e, is64);
    int r   = edge_val(et, e, is64);
    int deg = g_deg[dst * NREL + r];
    float inv = 1.0f / (float)deg;
    const __half* tp = g_T + (size_t)src * 1024 + r * HIDDEN + lane * 4;
    uint2 hv = *(const uint2*)tp;
    __half2 a = *(__half2*)&hv.x;
    __half2 b = *(__half2*)&hv.y;
    float2 fa = __half22float2(a);
    float2 fb = __half22float2(b);
    float4 v = make_float4(fa.x * inv, fa.y * inv, fb.x * inv, fb.y * inv);
    atomicAdd((float4*)&g_out[(size_t)dst * HIDDEN + lane * 4], v);
}

// ---------------- ReLU + LayerNorm ----------------
__global__ void k_ln(const float* __restrict__ gamma, const float* __restrict__ beta,
                     float* __restrict__ out, int N) {
    int gwarp = (blockIdx.x * blockDim.x + threadIdx.x) >> 5;
    int lane = threadIdx.x & 31;
    if (gwarp >= N) return;
    float4 v = *(const float4*)&g_out[(size_t)gwarp * HIDDEN + lane * 4];
    v.x = fmaxf(v.x, 0.f); v.y = fmaxf(v.y, 0.f);
    v.z = fmaxf(v.z, 0.f); v.w = fmaxf(v.w, 0.f);
    float s = v.x + v.y + v.z + v.w;
#pragma unroll
    for (int o = 16; o > 0; o >>= 1) s += __shfl_xor_sync(0xffffffffu, s, o);
    float mu = s * (1.0f / HIDDEN);
    float dx = v.x - mu, dy = v.y - mu, dz = v.z - mu, dw = v.w - mu;
    float ss = dx * dx + dy * dy + dz * dz + dw * dw;
#pragma unroll
    for (int o = 16; o > 0; o >>= 1) ss += __shfl_xor_sync(0xffffffffu, ss, o);
    float rs = rsqrtf(ss * (1.0f / HIDDEN) + 1e-5f);
    float4 gg = *(const float4*)&gamma[lane * 4];
    float4 bb = *(const float4*)&beta[lane * 4];
    float4 y = make_float4(dx * rs * gg.x + bb.x, dy * rs * gg.y + bb.y,
                           dz * rs * gg.z + bb.z, dw * rs * gg.w + bb.w);
    *(float4*)&out[(size_t)gwarp * HIDDEN + lane * 4] = y;
}

// ---------------- launch ----------------
extern "C" void kernel_launch(void* const* d_in, const int* in_sizes, int n_in,
                              void* d_out, int out_size) {
    const float* h     = (const float*)d_in[0];
    const void*  ei    = d_in[1];
    const void*  et    = d_in[2];
    const float* Wself = (const float*)d_in[3];
    const float* bself = (const float*)d_in[4];
    const float* Wrel  = (const float*)d_in[5];
    const float* gamma = (const float*)d_in[6];
    const float* beta  = (const float*)d_in[7];
    float* out = (float*)d_out;

    int N = in_sizes[0] / HIDDEN;
    int E = in_sizes[2];

    cudaFuncSetAttribute(k_gemm_rel, cudaFuncAttributeMaxDynamicSharedMemorySize, REL_SMEM);
    cudaFuncSetAttribute(k_gemm_self, cudaFuncAttributeMaxDynamicSharedMemorySize, SELF_SMEM);

    k_detect<<<1, 1>>>(ei);
    k_init<<<256, 256>>>(Wself, Wrel, N);
    k_count<<<(E + 1023) / 1024, 256>>>(ei, et, E);

    int mblocks = (N + 63) / 64;
    k_gemm_rel<<<mblocks, 128, REL_SMEM>>>(h, N);
    k_gemm_self<<<mblocks, 128, SELF_SMEM>>>(h, bself, N);

    int sblocks = (E * 32 + 255) / 256;
    k_scatter<<<sblocks, 256>>>(ei, et, E);

    int lblocks = (N * 32 + 255) / 256;
    k_ln<<<lblocks, 256>>>(gamma, beta, out, N);
}

// round 7
// speedup vs baseline: 2.9784x; 1.0125x over previous
#include <cuda_runtime.h>
#include <cuda_bf16.h>
#include <cuda_fp16.h>
#include <cstdint>

#define HIDDEN 128
#define NREL   8
#define MAXN   100000

// ---------------- device scratch ----------------
__device__ int   g_is64;
__device__ int   g_deg[MAXN * NREL];
__device__ __align__(16) __half g_T[(size_t)MAXN * 1024];     // relation messages (fp16)
__device__ __align__(16) float g_out[(size_t)MAXN * HIDDEN];  // pre-activation accumulator
__device__ __align__(16) __nv_bfloat16 g_Bh[128 * HIDDEN];    // W_self bf16 hi  [col][k]
__device__ __align__(16) __nv_bfloat16 g_Bl[128 * HIDDEN];    // W_self bf16 lo
__device__ __align__(16) __half g_Bf[1024 * HIDDEN];          // W_rel fp16      [col][k]

// ---------------- helpers ----------------
__device__ __forceinline__ uint32_t smem_u32(const void* p) {
    uint32_t a;
    asm("{ .reg .u64 t; cvta.to.shared.u64 t, %1; cvt.u32.u64 %0, t; }" : "=r"(a) : "l"(p));
    return a;
}
__device__ __forceinline__ void ldsm4(uint32_t* r, uint32_t addr) {
    asm volatile("ldmatrix.sync.aligned.m8n8.x4.shared.b16 {%0,%1,%2,%3}, [%4];"
                 : "=r"(r[0]), "=r"(r[1]), "=r"(r[2]), "=r"(r[3]) : "r"(addr));
}
__device__ __forceinline__ void mma_bf16(float* d, const uint32_t* a, const uint32_t* b) {
    asm volatile("mma.sync.aligned.m16n8k16.row.col.f32.bf16.bf16.f32 "
                 "{%0,%1,%2,%3}, {%4,%5,%6,%7}, {%8,%9}, {%0,%1,%2,%3};"
                 : "+f"(d[0]), "+f"(d[1]), "+f"(d[2]), "+f"(d[3])
                 : "r"(a[0]), "r"(a[1]), "r"(a[2]), "r"(a[3]), "r"(b[0]), "r"(b[1]));
}
__device__ __forceinline__ void mma_f16(float* d, const uint32_t* a, const uint32_t* b) {
    asm volatile("mma.sync.aligned.m16n8k16.row.col.f32.f16.f16.f32 "
                 "{%0,%1,%2,%3}, {%4,%5,%6,%7}, {%8,%9}, {%0,%1,%2,%3};"
                 : "+f"(d[0]), "+f"(d[1]), "+f"(d[2]), "+f"(d[3])
                 : "r"(a[0]), "r"(a[1]), "r"(a[2]), "r"(a[3]), "r"(b[0]), "r"(b[1]));
}
#define CP16(dst, src) asm volatile("cp.async.cg.shared.global [%0], [%1], 16;" :: "r"(dst), "l"(src))
#define CP_COMMIT()    asm volatile("cp.async.commit_group;")

static __device__ __forceinline__ unsigned short f2bf(float f) {
    __nv_bfloat16 b = __float2bfloat16(f);
    return *reinterpret_cast<unsigned short*>(&b);
}
static __device__ __forceinline__ float bfu2f(unsigned short u) {
    __nv_bfloat16 b;
    *reinterpret_cast<unsigned short*>(&b) = u;
    return __bfloat162float(b);
}

__device__ __forceinline__ int edge_val(const void* arr, int idx, int is64) {
    if (is64) return (int)((const long long*)arr)[idx];
    return ((const int*)arr)[idx];
}

// ---------------- init: detect dtype + zero deg + weight conversions ----------------
__global__ void k_init(const float* __restrict__ Wself, const float* __restrict__ Wrel,
                       const void* ei, int N) {
    if (blockIdx.x == 0 && threadIdx.x == 0) {
        const long long* p = (const long long*)ei;
        int ok64 = 1;
        for (int i = 0; i < 16; i++) {
            long long v = p[i];
            if (v < 0 || v >= (1LL << 31)) ok64 = 0;
        }
        g_is64 = ok64;
    }
    int stride = gridDim.x * blockDim.x;
    int i0 = blockIdx.x * blockDim.x + threadIdx.x;
    int nd = N * NREL;
    for (int t = i0; t < nd; t += stride) g_deg[t] = 0;
    // W_self: bf16 hi/lo split
    for (int t = i0; t < 2048; t += stride) {
        const float* src = Wself + (size_t)t * 8;
        float4 a = *(const float4*)src;
        float4 b = *(const float4*)(src + 4);
        float x[8] = {a.x, a.y, a.z, a.w, b.x, b.y, b.z, b.w};
        unsigned short hs[8], ls[8];
#pragma unroll
        for (int j = 0; j < 8; j++) {
            hs[j] = f2bf(x[j]);
            ls[j] = f2bf(x[j] - bfu2f(hs[j]));
        }
        uint4 H = make_uint4(hs[0] | (hs[1] << 16), hs[2] | (hs[3] << 16),
                             hs[4] | (hs[5] << 16), hs[6] | (hs[7] << 16));
        uint4 L = make_uint4(ls[0] | (ls[1] << 16), ls[2] | (ls[3] << 16),
                             ls[4] | (ls[5] << 16), ls[6] | (ls[7] << 16));
        *(uint4*)(g_Bh + (size_t)t * 8) = H;
        *(uint4*)(g_Bl + (size_t)t * 8) = L;
    }
    // W_rel: fp16
    for (int t = i0; t < 16384; t += stride) {
        const float* src = Wrel + (size_t)t * 8;
        float4 a = *(const float4*)src;
        float4 b = *(const float4*)(src + 4);
        __half2 h0 = __floats2half2_rn(a.x, a.y);
        __half2 h1 = __floats2half2_rn(a.z, a.w);
        __half2 h2 = __floats2half2_rn(b.x, b.y);
        __half2 h3 = __floats2half2_rn(b.z, b.w);
        uint4 V = make_uint4(*(uint32_t*)&h0, *(uint32_t*)&h1, *(uint32_t*)&h2, *(uint32_t*)&h3);
        *(uint4*)(g_Bf + (size_t)t * 8) = V;
    }
}

// ---------------- per-(dst, relation) degree counting ----------------
__global__ void k_count(const void* ei, const void* et, int E) {
    int is64 = g_is64;
    int base = (blockIdx.x * blockDim.x + threadIdx.x) * 4;
#pragma unroll
    for (int j = 0; j < 4; j++) {
        int e = base + j;
        if (e < E) {
            int dst = edge_val(ei, E + e, is64);
            int r   = edge_val(et, e, is64);
            atomicAdd(&g_deg[dst * NREL + r], 1);
        }
    }
}

// ================= relation GEMM: [M,128] x [128,1024] fp16 single-term =================
// 128 threads (2m x 2n warps), M-tile 128, warp tile 64x32. A fp16 resident (32KB),
// B dbl-buffered 16KB stages of 64 cols. smem 64KB -> 3 CTAs/SM.
#define REL_SMEM 65536
#define REL_STAGES 16

__global__ void __launch_bounds__(128, 3) k_gemm_rel(const float* __restrict__ h, int M) {
    extern __shared__ char smem[];
    uint32_t sb = smem_u32(smem);
    int tid = threadIdx.x, wid = tid >> 5, lane = tid & 31;
    int bx = blockIdx.x;
    int wm = wid >> 1, wn = wid & 1;
    int g = lane >> 2, tig = lane & 3;

    auto cpB = [&](int bn, int s) {
#pragma unroll
        for (int i = 0; i < 8; i++) {
            int id = i * 128 + tid;
            int j = id >> 4, c8 = id & 15;
            const void* src = g_Bf + (size_t)(bn * 64 + j) * 128 + c8 * 8;
            uint32_t dst = sb + 32768 + s * 16384 + j * 256 + ((c8 ^ (j & 7)) << 4);
            CP16(dst, src);
        }
    };
    cpB(0, 0); CP_COMMIT();
    cpB(1, 1); CP_COMMIT();

    // A: 128 rows fp32 -> fp16 -> swizzled smem (32 KB at offset 0)
#pragma unroll
    for (int i = 0; i < 32; i++) {
        int id = i * 128 + tid;
        int r = id >> 5, c4 = id & 31;
        int grow = bx * 128 + r;
        if (grow >= M) grow = M - 1;
        float4 v = *(const float4*)(h + (size_t)grow * HIDDEN + c4 * 4);
        __half2 p0 = __floats2half2_rn(v.x, v.y);
        __half2 p1 = __floats2half2_rn(v.z, v.w);
        uint2 V = make_uint2(*(uint32_t*)&p0, *(uint32_t*)&p1);
        int c8 = c4 >> 1;
        uint32_t off = r * 256 + ((c8 ^ (r & 7)) << 4) + ((c4 & 1) << 3);
        *(uint2*)(smem + off) = V;
    }

    for (int bn = 0; bn < REL_STAGES; bn++) {
        if (bn == REL_STAGES - 1) asm volatile("cp.async.wait_group 0;");
        else                      asm volatile("cp.async.wait_group 1;");
        __syncthreads();

        uint32_t bBase = sb + 32768 + (bn & 1) * 16384;
        float acc[4][4][4];
#pragma unroll
        for (int mf = 0; mf < 4; mf++)
#pragma unroll
            for (int nb = 0; nb < 4; nb++)
#pragma unroll
                for (int q = 0; q < 4; q++) acc[mf][nb][q] = 0.f;

#pragma unroll
        for (int ks = 0; ks < 8; ks++) {
            uint32_t af[4][4], bf[4][2];
#pragma unroll
            for (int mf = 0; mf < 4; mf++) {
                int row = wm * 64 + mf * 16 + (lane & 15);
                int c8 = ks * 2 + (lane >> 4);
                ldsm4(af[mf], sb + row * 256 + ((c8 ^ (row & 7)) << 4));
            }
#pragma unroll
            for (int p = 0; p < 2; p++) {
                int j = wn * 32 + p * 16 + (lane >> 4) * 8 + (lane & 7);
                int c8 = ks * 2 + ((lane >> 3) & 1);
                uint32_t t[4];
                ldsm4(t, bBase + j * 256 + ((c8 ^ (j & 7)) << 4));
                bf[2 * p][0] = t[0]; bf[2 * p][1] = t[1];
                bf[2 * p + 1][0] = t[2]; bf[2 * p + 1][1] = t[3];
            }
#pragma unroll
            for (int mf = 0; mf < 4; mf++)
#pragma unroll
                for (int nb = 0; nb < 4; nb++)
                    mma_f16(acc[mf][nb], af[mf], bf[nb]);
        }

        __syncthreads();
        if (bn < REL_STAGES - 2) { cpB(bn + 2, bn & 1); CP_COMMIT(); }

        int cn = wn * 32;
#pragma unroll
        for (int mf = 0; mf < 4; mf++) {
            int row0 = bx * 128 + wm * 64 + mf * 16 + g;
#pragma unroll
            for (int half = 0; half < 2; half++) {
                int row = row0 + half * 8;
                if (row < M) {
                    __half* o = g_T + (size_t)row * 1024 + bn * 64 + cn;
#pragma unroll
                    for (int nb = 0; nb < 4; nb++) {
                        int col = nb * 8 + tig * 2;
                        __half2 p = __floats2half2_rn(acc[mf][nb][half * 2 + 0],
                                                      acc[mf][nb][half * 2 + 1]);
                        *(uint32_t*)(o + col) = *(uint32_t*)&p;
                    }
                }
            }
        }
    }
}

// ================= self GEMM: [M,128] x [128,128] 3-term bf16 split =================
#define SELF_SMEM 98304

__global__ void __launch_bounds__(128, 2) k_gemm_self(const float* __restrict__ h,
                                                      const float* __restrict__ bself, int M) {
    extern __shared__ char smem[];
    uint32_t sb = smem_u32(smem);
    int tid = threadIdx.x, wid = tid >> 5, lane = tid & 31;
    int bx = blockIdx.x;
    int wm = wid >> 1, wn = wid & 1;
    int g = lane >> 2, tig = lane & 3;

    // B: 128 cols x 16 chunks, hi at 32768, lo at 65536
#pragma unroll
    for (int hf = 0; hf < 2; hf++) {
        const __nv_bfloat16* gsrc = hf ? g_Bl : g_Bh;
#pragma unroll
        for (int i = 0; i < 16; i++) {
            int id = i * 128 + tid;
            int j = id >> 4, c8 = id & 15;
            const void* src = gsrc + (size_t)j * 128 + c8 * 8;
            uint32_t dst = sb + 32768 + hf * 32768 + j * 256 + ((c8 ^ (j & 7)) << 4);
            CP16(dst, src);
        }
    }
    CP_COMMIT();

    // A: fp32 -> bf16 hi/lo -> swizzled smem (hi at 0, lo at 16384)
#pragma unroll
    for (int i = 0; i < 16; i++) {
        int id = i * 128 + tid;
        int r = id >> 5, c4 = id & 31;
        int grow = bx * 64 + r;
        if (grow >= M) grow = M - 1;
        float4 v = *(const float4*)(h + (size_t)grow * HIDDEN + c4 * 4);
        float x[4] = {v.x, v.y, v.z, v.w};
        unsigned short hs[4], ls[4];
#pragma unroll
        for (int j = 0; j < 4; j++) {
            hs[j] = f2bf(x[j]);
            ls[j] = f2bf(x[j] - bfu2f(hs[j]));
        }
        uint2 H = make_uint2(hs[0] | (hs[1] << 16), hs[2] | (hs[3] << 16));
        uint2 L = make_uint2(ls[0] | (ls[1] << 16), ls[2] | (ls[3] << 16));
        int c8 = c4 >> 1;
        uint32_t off = r * 256 + ((c8 ^ (r & 7)) << 4) + ((c4 & 1) << 3);
        *(uint2*)(smem + off) = H;
        *(uint2*)(smem + 16384 + off) = L;
    }
    asm volatile("cp.async.wait_group 0;");
    __syncthreads();

    float acc[2][8][4];
#pragma unroll
    for (int mf = 0; mf < 2; mf++)
#pragma unroll
        for (int nb = 0; nb < 8; nb++)
#pragma unroll
            for (int q = 0; q < 4; q++) acc[mf][nb][q] = 0.f;

#pragma unroll
    for (int ks = 0; ks < 8; ks++) {
        uint32_t ah[2][4], al[2][4], bh[8][2], bl[8][2];
#pragma unroll
        for (int mf = 0; mf < 2; mf++) {
            int row = wm * 32 + mf * 16 + (lane & 15);
            int c8 = ks * 2 + (lane >> 4);
            uint32_t ad = sb + row * 256 + ((c8 ^ (row & 7)) << 4);
            ldsm4(ah[mf], ad);
            ldsm4(al[mf], ad + 16384);
        }
#pragma unroll
        for (int p = 0; p < 4; p++) {
            int j = wn * 64 + p * 16 + (lane >> 4) * 8 + (lane & 7);
            int c8 = ks * 2 + ((lane >> 3) & 1);
            uint32_t bd = sb + 32768 + j * 256 + ((c8 ^ (j & 7)) << 4);
            uint32_t t[4];
            ldsm4(t, bd);
            bh[2 * p][0] = t[0]; bh[2 * p][1] = t[1];
            bh[2 * p + 1][0] = t[2]; bh[2 * p + 1][1] = t[3];
            ldsm4(t, bd + 32768);
            bl[2 * p][0] = t[0]; bl[2 * p][1] = t[1];
            bl[2 * p + 1][0] = t[2]; bl[2 * p + 1][1] = t[3];
        }
#pragma unroll
        for (int mf = 0; mf < 2; mf++)
#pragma unroll
            for (int nb = 0; nb < 8; nb++) {
                mma_bf16(acc[mf][nb], ah[mf], bh[nb]);
                mma_bf16(acc[mf][nb], ah[mf], bl[nb]);
                mma_bf16(acc[mf][nb], al[mf], bh[nb]);
            }
    }

#pragma unroll
    for (int mf = 0; mf < 2; mf++) {
        int row0 = bx * 64 + wm * 32 + mf * 16 + g;
#pragma unroll
        for (int half = 0; half < 2; half++) {
            int row = row0 + half * 8;
            if (row < M) {
                float* o = g_out + (size_t)row * HIDDEN + wn * 64;
                const float* bs = bself + wn * 64;
#pragma unroll
                for (int nb = 0; nb < 8; nb++) {
                    int col = nb * 8 + tig * 2;
                    float2 v;
                    v.x = acc[mf][nb][half * 2 + 0] + __ldg(bs + col);
                    v.y = acc[mf][nb][half * 2 + 1] + __ldg(bs + col + 1);
                    *(float2*)(o + col) = v;
                }
            }
        }
    }
}

// ---------------- edge scatter: out[dst] += T[src, r] / deg (fp16 gather) ----------------
__global__ void k_scatter(const void* ei, const void* et, int E) {
    int is64 = g_is64;
    int gwarp = (blockIdx.x * blockDim.x + threadIdx.x) >> 5;
    int lane = threadIdx.x & 31;
    if (gwarp >= E) return;
    int e = gwarp;
    int src = edge_val(ei, e, is64);
    int dst = edge_val(ei, E + e, is64);
    int r   = edge_val(et, e, is64);
    int deg = g_deg[dst * NREL + r];
    float inv = 1.0f / (float)deg;
    const __half* tp = g_T + (size_t)src * 1024 + r * HIDDEN + lane * 4;
    uint2 hv = *(const uint2*)tp;
    __half2 a = *(__half2*)&hv.x;
    __half2 b = *(__half2*)&hv.y;
    float2 fa = __half22float2(a);
    float2 fb = __half22float2(b);
    float4 v = make_float4(fa.x * inv, fa.y * inv, fb.x * inv, fb.y * inv);
    atomicAdd((float4*)&g_out[(size_t)dst * HIDDEN + lane * 4], v);
}

// ---------------- ReLU + LayerNorm ----------------
__global__ void k_ln(const float* __restrict__ gamma, const float* __restrict__ beta,
                     float* __restrict__ out, int N) {
    int gwarp = (blockIdx.x * blockDim.x + threadIdx.x) >> 5;
    int lane = threadIdx.x & 31;
    if (gwarp >= N) return;
    float4 v = *(const float4*)&g_out[(size_t)gwarp * HIDDEN + lane * 4];
    v.x = fmaxf(v.x, 0.f); v.y = fmaxf(v.y, 0.f);
    v.z = fmaxf(v.z, 0.f); v.w = fmaxf(v.w, 0.f);
    float s = v.x + v.y + v.z + v.w;
#pragma unroll
    for (int o = 16; o > 0; o >>= 1) s += __shfl_xor_sync(0xffffffffu, s, o);
    float mu = s * (1.0f / HIDDEN);
    float dx = v.x - mu, dy = v.y - mu, dz = v.z - mu, dw = v.w - mu;
    float ss = dx * dx + dy * dy + dz * dz + dw * dw;
#pragma unroll
    for (int o = 16; o > 0; o >>= 1) ss += __shfl_xor_sync(0xffffffffu, ss, o);
    float rs = rsqrtf(ss * (1.0f / HIDDEN) + 1e-5f);
    float4 gg = *(const float4*)&gamma[lane * 4];
    float4 bb = *(const float4*)&beta[lane * 4];
    float4 y = make_float4(dx * rs * gg.x + bb.x, dy * rs * gg.y + bb.y,
                           dz * rs * gg.z + bb.z, dw * rs * gg.w + bb.w);
    *(float4*)&out[(size_t)gwarp * HIDDEN + lane * 4] = y;
}

// ---------------- launch ----------------
extern "C" void kernel_launch(void* const* d_in, const int* in_sizes, int n_in,
                              void* d_out, int out_size) {
    const float* h     = (const float*)d_in[0];
    const void*  ei    = d_in[1];
    const void*  et    = d_in[2];
    const float* Wself = (const float*)d_in[3];
    const float* bself = (const float*)d_in[4];
    const float* Wrel  = (const float*)d_in[5];
    const float* gamma = (const float*)d_in[6];
    const float* beta  = (const float*)d_in[7];
    float* out = (float*)d_out;

    int N = in_sizes[0] / HIDDEN;
    int E = in_sizes[2];

    cudaFuncSetAttribute(k_gemm_rel, cudaFuncAttributeMaxDynamicSharedMemorySize, REL_SMEM);
    cudaFuncSetAttribute(k_gemm_self, cudaFuncAttributeMaxDynamicSharedMemorySize, SELF_SMEM);

    k_init<<<256, 256>>>(Wself, Wrel, ei, N);
    k_count<<<(E + 1023) / 1024, 256>>>(ei, et, E);

    int rblocks = (N + 127) / 128;
    k_gemm_rel<<<rblocks, 128, REL_SMEM>>>(h, N);
    int sblocks128 = (N + 63) / 64;
    k_gemm_self<<<sblocks128, 128, SELF_SMEM>>>(h, bself, N);

    int sblocks = (E * 32 + 255) / 256;
    k_scatter<<<sblocks, 256>>>(ei, et, E);

    int lblocks = (N * 32 + 255) / 256;
    k_ln<<<lblocks, 256>>>(gamma, beta, out, N);
}

// round 8
// speedup vs baseline: 3.6966x; 1.2411x over previous
#include <cuda_runtime.h>
#include <cuda_bf16.h>
#include <cuda_fp16.h>
#include <cstdint>

#define HIDDEN 128
#define NREL   8
#define MAXN   100000
#define MAXE   600000

// ---------------- device scratch ----------------
__device__ int   g_is64;
__device__ int   g_total;
__device__ __align__(16) int g_deg[MAXN * NREL];
__device__ int   g_off[MAXN];      // CSR range start per dst (unordered ranges)
__device__ int   g_cur[MAXN];      // placement cursor
__device__ int   g_len[MAXN];      // per-dst degree
__device__ int   g_edge[MAXE];     // packed (src<<3)|r
__device__ __align__(16) __half g_T[(size_t)MAXN * 1024];     // relation messages (fp16)
__device__ __align__(16) float g_out[(size_t)MAXN * HIDDEN];  // self term (fp32)
__device__ __align__(16) __half g_Bf[1152 * HIDDEN];          // [W_self; W_rel] fp16 [col][k]

// ---------------- helpers ----------------
__device__ __forceinline__ uint32_t smem_u32(const void* p) {
    uint32_t a;
    asm("{ .reg .u64 t; cvta.to.shared.u64 t, %1; cvt.u32.u64 %0, t; }" : "=r"(a) : "l"(p));
    return a;
}
__device__ __forceinline__ void ldsm4(uint32_t* r, uint32_t addr) {
    asm volatile("ldmatrix.sync.aligned.m8n8.x4.shared.b16 {%0,%1,%2,%3}, [%4];"
                 : "=r"(r[0]), "=r"(r[1]), "=r"(r[2]), "=r"(r[3]) : "r"(addr));
}
__device__ __forceinline__ void mma_f16(float* d, const uint32_t* a, const uint32_t* b) {
    asm volatile("mma.sync.aligned.m16n8k16.row.col.f32.f16.f16.f32 "
                 "{%0,%1,%2,%3}, {%4,%5,%6,%7}, {%8,%9}, {%0,%1,%2,%3};"
                 : "+f"(d[0]), "+f"(d[1]), "+f"(d[2]), "+f"(d[3])
                 : "r"(a[0]), "r"(a[1]), "r"(a[2]), "r"(a[3]), "r"(b[0]), "r"(b[1]));
}
#define CP16(dst, src) asm volatile("cp.async.cg.shared.global [%0], [%1], 16;" :: "r"(dst), "l"(src))
#define CP_COMMIT()    asm volatile("cp.async.commit_group;")

__device__ __forceinline__ int edge_val(const void* arr, int idx, int is64) {
    if (is64) return (int)((const long long*)arr)[idx];
    return ((const int*)arr)[idx];
}

// ---------------- init: detect dtype + zero deg + fp16 weight pack ----------------
__global__ void k_init(const float* __restrict__ Wself, const float* __restrict__ Wrel,
                       const void* ei, int N) {
    if (blockIdx.x == 0 && threadIdx.x == 0) {
        const long long* p = (const long long*)ei;
        int ok64 = 1;
        for (int i = 0; i < 16; i++) {
            long long v = p[i];
            if (v < 0 || v >= (1LL << 31)) ok64 = 0;
        }
        g_is64 = ok64;
        g_total = 0;
    }
    int stride = gridDim.x * blockDim.x;
    int i0 = blockIdx.x * blockDim.x + threadIdx.x;
    int nd = N * NREL;
    for (int t = i0; t < nd; t += stride) g_deg[t] = 0;
    // pack [W_self(2048 chunks); W_rel(16384 chunks)] -> g_Bf fp16
    for (int t = i0; t < 18432; t += stride) {
        const float* src = (t < 2048) ? (Wself + (size_t)t * 8) : (Wrel + (size_t)(t - 2048) * 8);
        float4 a = *(const float4*)src;
        float4 b = *(const float4*)(src + 4);
        __half2 h0 = __floats2half2_rn(a.x, a.y);
        __half2 h1 = __floats2half2_rn(a.z, a.w);
        __half2 h2 = __floats2half2_rn(b.x, b.y);
        __half2 h3 = __floats2half2_rn(b.z, b.w);
        uint4 V = make_uint4(*(uint32_t*)&h0, *(uint32_t*)&h1, *(uint32_t*)&h2, *(uint32_t*)&h3);
        *(uint4*)(g_Bf + (size_t)t * 8) = V;
    }
}

// ---------------- per-(dst, relation) degree counting ----------------
__global__ void k_count(const void* ei, const void* et, int E) {
    int is64 = g_is64;
    int base = (blockIdx.x * blockDim.x + threadIdx.x) * 4;
#pragma unroll
    for (int j = 0; j < 4; j++) {
        int e = base + j;
        if (e < E) {
            int dst = edge_val(ei, E + e, is64);
            int r   = edge_val(et, e, is64);
            atomicAdd(&g_deg[dst * NREL + r], 1);
        }
    }
}

// ---------------- CSR offsets: unordered disjoint ranges via warp-aggregated atomic ----------------
__global__ void k_offsets(int N) {
    int dst = blockIdx.x * blockDim.x + threadIdx.x;
    int lane = threadIdx.x & 31;
    int dd = 0;
    if (dst < N) {
        int4 a = *(const int4*)&g_deg[dst * 8];
        int4 b = *(const int4*)&g_deg[dst * 8 + 4];
        dd = a.x + a.y + a.z + a.w + b.x + b.y + b.z + b.w;
    }
    int v = dd;
#pragma unroll
    for (int o = 1; o < 32; o <<= 1) {
        int t = __shfl_up_sync(0xffffffffu, v, o);
        if (lane >= o) v += t;
    }
    int total = __shfl_sync(0xffffffffu, v, 31);
    int base = 0;
    if (lane == 31) base = atomicAdd(&g_total, total);
    base = __shfl_sync(0xffffffffu, base, 31);
    int start = base + v - dd;
    if (dst < N) {
        g_off[dst] = start;
        g_cur[dst] = start;
        g_len[dst] = dd;
    }
}

// ---------------- edge placement into CSR ----------------
__global__ void k_place(const void* ei, const void* et, int E) {
    int is64 = g_is64;
    int base = (blockIdx.x * blockDim.x + threadIdx.x) * 4;
#pragma unroll
    for (int j = 0; j < 4; j++) {
        int e = base + j;
        if (e < E) {
            int src = edge_val(ei, e, is64);
            int dst = edge_val(ei, E + e, is64);
            int r   = edge_val(et, e, is64);
            int pos = atomicAdd(&g_cur[dst], 1);
            g_edge[pos] = (src << 3) | r;
        }
    }
}

// ================= fused GEMM: [M,128] x [128,1152] fp16 =================
// Stages 0,1 (cols 0..127 = W_self) -> g_out fp32 + bias; stages 2..17 -> g_T fp16.
// 128 threads (2m x 2n warps), M-tile 128, warp tile 64x32. A fp16 resident (32KB),
// B dbl-buffered 16KB stages. smem 64KB -> 3 CTAs/SM.
#define GM_SMEM 65536
#define GM_STAGES 18

__global__ void __launch_bounds__(128, 3) k_gemm(const float* __restrict__ h,
                                                 const float* __restrict__ bself, int M) {
    extern __shared__ char smem[];
    uint32_t sb = smem_u32(smem);
    int tid = threadIdx.x, wid = tid >> 5, lane = tid & 31;
    int bx = blockIdx.x;
    int wm = wid >> 1, wn = wid & 1;
    int g = lane >> 2, tig = lane & 3;

    auto cpB = [&](int bn, int s) {
#pragma unroll
        for (int i = 0; i < 8; i++) {
            int id = i * 128 + tid;
            int j = id >> 4, c8 = id & 15;
            const void* src = g_Bf + (size_t)(bn * 64 + j) * 128 + c8 * 8;
            uint32_t dst = sb + 32768 + s * 16384 + j * 256 + ((c8 ^ (j & 7)) << 4);
            CP16(dst, src);
        }
    };
    cpB(0, 0); CP_COMMIT();
    cpB(1, 1); CP_COMMIT();

    // A: 128 rows fp32 -> fp16 -> swizzled smem
#pragma unroll
    for (int i = 0; i < 32; i++) {
        int id = i * 128 + tid;
        int r = id >> 5, c4 = id & 31;
        int grow = bx * 128 + r;
        if (grow >= M) grow = M - 1;
        float4 v = *(const float4*)(h + (size_t)grow * HIDDEN + c4 * 4);
        __half2 p0 = __floats2half2_rn(v.x, v.y);
        __half2 p1 = __floats2half2_rn(v.z, v.w);
        uint2 V = make_uint2(*(uint32_t*)&p0, *(uint32_t*)&p1);
        int c8 = c4 >> 1;
        uint32_t off = r * 256 + ((c8 ^ (r & 7)) << 4) + ((c4 & 1) << 3);
        *(uint2*)(smem + off) = V;
    }

    for (int bn = 0; bn < GM_STAGES; bn++) {
        if (bn == GM_STAGES - 1) asm volatile("cp.async.wait_group 0;");
        else                     asm volatile("cp.async.wait_group 1;");
        __syncthreads();

        uint32_t bBase = sb + 32768 + (bn & 1) * 16384;
        float acc[4][4][4];
#pragma unroll
        for (int mf = 0; mf < 4; mf++)
#pragma unroll
            for (int nb = 0; nb < 4; nb++)
#pragma unroll
                for (int q = 0; q < 4; q++) acc[mf][nb][q] = 0.f;

#pragma unroll
        for (int ks = 0; ks < 8; ks++) {
            uint32_t af[4][4], bf[4][2];
#pragma unroll
            for (int mf = 0; mf < 4; mf++) {
                int row = wm * 64 + mf * 16 + (lane & 15);
                int c8 = ks * 2 + (lane >> 4);
                ldsm4(af[mf], sb + row * 256 + ((c8 ^ (row & 7)) << 4));
            }
#pragma unroll
            for (int p = 0; p < 2; p++) {
                int j = wn * 32 + p * 16 + (lane >> 4) * 8 + (lane & 7);
                int c8 = ks * 2 + ((lane >> 3) & 1);
                uint32_t t[4];
                ldsm4(t, bBase + j * 256 + ((c8 ^ (j & 7)) << 4));
                bf[2 * p][0] = t[0]; bf[2 * p][1] = t[1];
                bf[2 * p + 1][0] = t[2]; bf[2 * p + 1][1] = t[3];
            }
#pragma unroll
            for (int mf = 0; mf < 4; mf++)
#pragma unroll
                for (int nb = 0; nb < 4; nb++)
                    mma_f16(acc[mf][nb], af[mf], bf[nb]);
        }

        __syncthreads();
        if (bn < GM_STAGES - 2) { cpB(bn + 2, bn & 1); CP_COMMIT(); }

        int cn = wn * 32;
#pragma unroll
        for (int mf = 0; mf < 4; mf++) {
            int row0 = bx * 128 + wm * 64 + mf * 16 + g;
#pragma unroll
            for (int half = 0; half < 2; half++) {
                int row = row0 + half * 8;
                if (row < M) {
                    if (bn < 2) {
                        float* o = g_out + (size_t)row * HIDDEN + bn * 64 + cn;
                        const float* bs = bself + bn * 64 + cn;
#pragma unroll
                        for (int nb = 0; nb < 4; nb++) {
                            int col = nb * 8 + tig * 2;
                            float2 v;
                            v.x = acc[mf][nb][half * 2 + 0] + __ldg(bs + col);
                            v.y = acc[mf][nb][half * 2 + 1] + __ldg(bs + col + 1);
                            *(float2*)(o + col) = v;
                        }
                    } else {
                        __half* o = g_T + (size_t)row * 1024 + (bn - 2) * 64 + cn;
#pragma unroll
                        for (int nb = 0; nb < 4; nb++) {
                            int col = nb * 8 + tig * 2;
                            __half2 p = __floats2half2_rn(acc[mf][nb][half * 2 + 0],
                                                          acc[mf][nb][half * 2 + 1]);
                            *(uint32_t*)(o + col) = *(uint32_t*)&p;
                        }
                    }
                }
            }
        }
    }
}

// ---------------- aggregation + ReLU + LayerNorm (warp per node, no atomics) ----------------
__global__ void __launch_bounds__(256) k_agg(const float* __restrict__ gamma,
                                             const float* __restrict__ beta,
                                             float* __restrict__ out, int N) {
    int dst = blockIdx.x * 8 + (threadIdx.x >> 5);
    int lane = threadIdx.x & 31;
    if (dst >= N) return;
    int off = g_off[dst];
    int len = g_len[dst];

    float a0 = 0.f, a1 = 0.f, a2 = 0.f, a3 = 0.f;
    int val = (len > 0) ? __ldg(&g_edge[off]) : 0;
    for (int i = 0; i < len; i++) {
        int nval = (i + 1 < len) ? __ldg(&g_edge[off + i + 1]) : 0;
        int src = val >> 3, r = val & 7;
        float inv = 1.0f / (float)__ldg(&g_deg[dst * 8 + r]);
        const __half* tp = g_T + (size_t)src * 1024 + r * HIDDEN + lane * 4;
        uint2 hv = *(const uint2*)tp;
        __half2 p0 = *(__half2*)&hv.x;
        __half2 p1 = *(__half2*)&hv.y;
        float2 f0 = __half22float2(p0);
        float2 f1 = __half22float2(p1);
        a0 += inv * f0.x; a1 += inv * f0.y;
        a2 += inv * f1.x; a3 += inv * f1.y;
        val = nval;
    }

    float4 s = *(const float4*)&g_out[(size_t)dst * HIDDEN + lane * 4];
    float vx = fmaxf(s.x + a0, 0.f);
    float vy = fmaxf(s.y + a1, 0.f);
    float vz = fmaxf(s.z + a2, 0.f);
    float vw = fmaxf(s.w + a3, 0.f);

    float sum = vx + vy + vz + vw;
#pragma unroll
    for (int o = 16; o > 0; o >>= 1) sum += __shfl_xor_sync(0xffffffffu, sum, o);
    float mu = sum * (1.0f / HIDDEN);
    float dx = vx - mu, dy = vy - mu, dz = vz - mu, dw = vw - mu;
    float ss = dx * dx + dy * dy + dz * dz + dw * dw;
#pragma unroll
    for (int o = 16; o > 0; o >>= 1) ss += __shfl_xor_sync(0xffffffffu, ss, o);
    float rs = rsqrtf(ss * (1.0f / HIDDEN) + 1e-5f);
    float4 gg = *(const float4*)&gamma[lane * 4];
    float4 bb = *(const float4*)&beta[lane * 4];
    float4 y = make_float4(dx * rs * gg.x + bb.x, dy * rs * gg.y + bb.y,
                           dz * rs * gg.z + bb.z, dw * rs * gg.w + bb.w);
    *(float4*)&out[(size_t)dst * HIDDEN + lane * 4] = y;
}

// ---------------- launch ----------------
extern "C" void kernel_launch(void* const* d_in, const int* in_sizes, int n_in,
                              void* d_out, int out_size) {
    const float* h     = (const float*)d_in[0];
    const void*  ei    = d_in[1];
    const void*  et    = d_in[2];
    const float* Wself = (const float*)d_in[3];
    const float* bself = (const float*)d_in[4];
    const float* Wrel  = (const float*)d_in[5];
    const float* gamma = (const float*)d_in[6];
    const float* beta  = (const float*)d_in[7];
    float* out = (float*)d_out;

    int N = in_sizes[0] / HIDDEN;
    int E = in_sizes[2];

    cudaFuncSetAttribute(k_gemm, cudaFuncAttributeMaxDynamicSharedMemorySize, GM_SMEM);

    k_init<<<256, 256>>>(Wself, Wrel, ei, N);
    k_count<<<(E + 1023) / 1024, 256>>>(ei, et, E);
    k_offsets<<<(N + 255) / 256, 256>>>(N);
    k_place<<<(E + 1023) / 1024, 256>>>(ei, et, E);

    int gblocks = (N + 127) / 128;
    k_gemm<<<gblocks, 128, GM_SMEM>>>(h, bself, N);

    int ablocks = (N + 7) / 8;
    k_agg<<<ablocks, 256>>>(gamma, beta, out, N);
}

// round 9
// speedup vs baseline: 4.0020x; 1.0826x over previous
#include <cuda_runtime.h>
#include <cuda_bf16.h>
#include <cuda_fp16.h>
#include <cstdint>

#define HIDDEN 128
#define NREL   8
#define MAXN   100000
#define MAXE   600000

// ---------------- device scratch ----------------
__device__ int   g_is64;
__device__ int   g_total;
__device__ __align__(16) int g_deg[MAXN * NREL];
__device__ int   g_off[MAXN];      // CSR range start per dst (unordered ranges)
__device__ int   g_cur[MAXN];      // placement cursor
__device__ int   g_len[MAXN];      // per-dst degree
__device__ int   g_edge[MAXE];     // packed (src<<3)|r
__device__ __align__(16) __half g_T[(size_t)MAXN * 1024];     // relation messages (fp16)
__device__ __align__(16) float g_out[(size_t)MAXN * HIDDEN];  // self term (fp32)
__device__ __align__(16) __half g_Bf[1152 * HIDDEN];          // [W_self; W_rel] fp16 [col][k]

// ---------------- helpers ----------------
__device__ __forceinline__ uint32_t smem_u32(const void* p) {
    uint32_t a;
    asm("{ .reg .u64 t; cvta.to.shared.u64 t, %1; cvt.u32.u64 %0, t; }" : "=r"(a) : "l"(p));
    return a;
}
__device__ __forceinline__ void ldsm4(uint32_t* r, uint32_t addr) {
    asm volatile("ldmatrix.sync.aligned.m8n8.x4.shared.b16 {%0,%1,%2,%3}, [%4];"
                 : "=r"(r[0]), "=r"(r[1]), "=r"(r[2]), "=r"(r[3]) : "r"(addr));
}
__device__ __forceinline__ void mma_f16(float* d, const uint32_t* a, const uint32_t* b) {
    asm volatile("mma.sync.aligned.m16n8k16.row.col.f32.f16.f16.f32 "
                 "{%0,%1,%2,%3}, {%4,%5,%6,%7}, {%8,%9}, {%0,%1,%2,%3};"
                 : "+f"(d[0]), "+f"(d[1]), "+f"(d[2]), "+f"(d[3])
                 : "r"(a[0]), "r"(a[1]), "r"(a[2]), "r"(a[3]), "r"(b[0]), "r"(b[1]));
}
#define CP16(dst, src) asm volatile("cp.async.cg.shared.global [%0], [%1], 16;" :: "r"(dst), "l"(src))
#define CP_COMMIT()    asm volatile("cp.async.commit_group;")

__device__ __forceinline__ int edge_val(const void* arr, int idx, int is64) {
    if (is64) return (int)((const long long*)arr)[idx];
    return ((const int*)arr)[idx];
}

// ---------------- init: detect dtype + zero deg + fp16 weight pack ----------------
__global__ void k_init(const float* __restrict__ Wself, const float* __restrict__ Wrel,
                       const void* ei, int N) {
    if (blockIdx.x == 0 && threadIdx.x == 0) {
        const long long* p = (const long long*)ei;
        int ok64 = 1;
        for (int i = 0; i < 16; i++) {
            long long v = p[i];
            if (v < 0 || v >= (1LL << 31)) ok64 = 0;
        }
        g_is64 = ok64;
        g_total = 0;
    }
    int stride = gridDim.x * blockDim.x;
    int i0 = blockIdx.x * blockDim.x + threadIdx.x;
    int nd = N * NREL;
    for (int t = i0; t < nd; t += stride) g_deg[t] = 0;
    for (int t = i0; t < 18432; t += stride) {
        const float* src = (t < 2048) ? (Wself + (size_t)t * 8) : (Wrel + (size_t)(t - 2048) * 8);
        float4 a = *(const float4*)src;
        float4 b = *(const float4*)(src + 4);
        __half2 h0 = __floats2half2_rn(a.x, a.y);
        __half2 h1 = __floats2half2_rn(a.z, a.w);
        __half2 h2 = __floats2half2_rn(b.x, b.y);
        __half2 h3 = __floats2half2_rn(b.z, b.w);
        uint4 V = make_uint4(*(uint32_t*)&h0, *(uint32_t*)&h1, *(uint32_t*)&h2, *(uint32_t*)&h3);
        *(uint4*)(g_Bf + (size_t)t * 8) = V;
    }
}

// ---------------- per-(dst, relation) degree counting ----------------
__global__ void k_count(const void* ei, const void* et, int E) {
    int is64 = g_is64;
    int base = (blockIdx.x * blockDim.x + threadIdx.x) * 4;
#pragma unroll
    for (int j = 0; j < 4; j++) {
        int e = base + j;
        if (e < E) {
            int dst = edge_val(ei, E + e, is64);
            int r   = edge_val(et, e, is64);
            atomicAdd(&g_deg[dst * NREL + r], 1);
        }
    }
}

// ---------------- CSR offsets ----------------
__global__ void k_offsets(int N) {
    int dst = blockIdx.x * blockDim.x + threadIdx.x;
    int lane = threadIdx.x & 31;
    int dd = 0;
    if (dst < N) {
        int4 a = *(const int4*)&g_deg[dst * 8];
        int4 b = *(const int4*)&g_deg[dst * 8 + 4];
        dd = a.x + a.y + a.z + a.w + b.x + b.y + b.z + b.w;
    }
    int v = dd;
#pragma unroll
    for (int o = 1; o < 32; o <<= 1) {
        int t = __shfl_up_sync(0xffffffffu, v, o);
        if (lane >= o) v += t;
    }
    int total = __shfl_sync(0xffffffffu, v, 31);
    int base = 0;
    if (lane == 31) base = atomicAdd(&g_total, total);
    base = __shfl_sync(0xffffffffu, base, 31);
    int start = base + v - dd;
    if (dst < N) {
        g_off[dst] = start;
        g_cur[dst] = start;
        g_len[dst] = dd;
    }
}

// ---------------- edge placement ----------------
__global__ void k_place(const void* ei, const void* et, int E) {
    int is64 = g_is64;
    int base = (blockIdx.x * blockDim.x + threadIdx.x) * 4;
#pragma unroll
    for (int j = 0; j < 4; j++) {
        int e = base + j;
        if (e < E) {
            int src = edge_val(ei, e, is64);
            int dst = edge_val(ei, E + e, is64);
            int r   = edge_val(et, e, is64);
            int pos = atomicAdd(&g_cur[dst], 1);
            g_edge[pos] = (src << 3) | r;
        }
    }
}

// ================= fused GEMM: [M,128] x [128,1152] fp16 =================
// CTA 128x128 tile, 4 warps (2m x 2n), warp tile 64x64. A fp16 resident (32KB),
// B dbl-buffered 32KB stages of 128 cols (9 stages). smem 96KB -> 2 CTAs/SM.
// Stage 0 (W_self) -> g_out fp32 + bias; stages 1..8 -> g_T fp16.
#define GM_SMEM 98304
#define GM_STAGES 9

__global__ void __launch_bounds__(128, 2) k_gemm(const float* __restrict__ h,
                                                 const float* __restrict__ bself, int M) {
    extern __shared__ char smem[];
    uint32_t sb = smem_u32(smem);
    int tid = threadIdx.x, wid = tid >> 5, lane = tid & 31;
    int bx = blockIdx.x;
    int wm = wid >> 1, wn = wid & 1;
    int g = lane >> 2, tig = lane & 3;

    auto cpB = [&](int bn, int s) {
#pragma unroll
        for (int i = 0; i < 16; i++) {
            int id = i * 128 + tid;
            int j = id >> 4, c8 = id & 15;
            const void* src = g_Bf + (size_t)(bn * 128 + j) * 128 + c8 * 8;
            uint32_t dst = sb + 32768 + s * 32768 + j * 256 + ((c8 ^ (j & 7)) << 4);
            CP16(dst, src);
        }
    };
    cpB(0, 0); CP_COMMIT();
    cpB(1, 1); CP_COMMIT();

    // A: 128 rows fp32 -> fp16 -> swizzled smem (32 KB)
#pragma unroll
    for (int i = 0; i < 32; i++) {
        int id = i * 128 + tid;
        int r = id >> 5, c4 = id & 31;
        int grow = bx * 128 + r;
        if (grow >= M) grow = M - 1;
        float4 v = *(const float4*)(h + (size_t)grow * HIDDEN + c4 * 4);
        __half2 p0 = __floats2half2_rn(v.x, v.y);
        __half2 p1 = __floats2half2_rn(v.z, v.w);
        uint2 V = make_uint2(*(uint32_t*)&p0, *(uint32_t*)&p1);
        int c8 = c4 >> 1;
        uint32_t off = r * 256 + ((c8 ^ (r & 7)) << 4) + ((c4 & 1) << 3);
        *(uint2*)(smem + off) = V;
    }

    for (int bn = 0; bn < GM_STAGES; bn++) {
        if (bn == GM_STAGES - 1) asm volatile("cp.async.wait_group 0;");
        else                     asm volatile("cp.async.wait_group 1;");
        __syncthreads();

        uint32_t bBase = sb + 32768 + (bn & 1) * 32768;
        float acc[4][8][4];
#pragma unroll
        for (int mf = 0; mf < 4; mf++)
#pragma unroll
            for (int nb = 0; nb < 8; nb++)
#pragma unroll
                for (int q = 0; q < 4; q++) acc[mf][nb][q] = 0.f;

#pragma unroll
        for (int ks = 0; ks < 8; ks++) {
            uint32_t af[4][4], bf[8][2];
#pragma unroll
            for (int mf = 0; mf < 4; mf++) {
                int row = wm * 64 + mf * 16 + (lane & 15);
                int c8 = ks * 2 + (lane >> 4);
                ldsm4(af[mf], sb + row * 256 + ((c8 ^ (row & 7)) << 4));
            }
#pragma unroll
            for (int p = 0; p < 4; p++) {
                int j = wn * 64 + p * 16 + (lane >> 4) * 8 + (lane & 7);
                int c8 = ks * 2 + ((lane >> 3) & 1);
                uint32_t t[4];
                ldsm4(t, bBase + j * 256 + ((c8 ^ (j & 7)) << 4));
                bf[2 * p][0] = t[0]; bf[2 * p][1] = t[1];
                bf[2 * p + 1][0] = t[2]; bf[2 * p + 1][1] = t[3];
            }
#pragma unroll
            for (int mf = 0; mf < 4; mf++)
#pragma unroll
                for (int nb = 0; nb < 8; nb++)
                    mma_f16(acc[mf][nb], af[mf], bf[nb]);
        }

        __syncthreads();
        if (bn < GM_STAGES - 2) { cpB(bn + 2, bn & 1); CP_COMMIT(); }

        int cn = wn * 64;
#pragma unroll
        for (int mf = 0; mf < 4; mf++) {
            int row0 = bx * 128 + wm * 64 + mf * 16 + g;
#pragma unroll
            for (int half = 0; half < 2; half++) {
                int row = row0 + half * 8;
                if (row < M) {
                    if (bn == 0) {
                        float* o = g_out + (size_t)row * HIDDEN + cn;
                        const float* bs = bself + cn;
#pragma unroll
                        for (int nb = 0; nb < 8; nb++) {
                            int col = nb * 8 + tig * 2;
                            float2 v;
                            v.x = acc[mf][nb][half * 2 + 0] + __ldg(bs + col);
                            v.y = acc[mf][nb][half * 2 + 1] + __ldg(bs + col + 1);
                            *(float2*)(o + col) = v;
                        }
                    } else {
                        __half* o = g_T + (size_t)row * 1024 + (bn - 1) * 128 + cn;
#pragma unroll
                        for (int nb = 0; nb < 8; nb++) {
                            int col = nb * 8 + tig * 2;
                            __half2 p = __floats2half2_rn(acc[mf][nb][half * 2 + 0],
                                                          acc[mf][nb][half * 2 + 1]);
                            *(uint32_t*)(o + col) = *(uint32_t*)&p;
                        }
                    }
                }
            }
        }
    }
}

// ---------------- aggregation + ReLU + LayerNorm (warp per node) ----------------
__global__ void __launch_bounds__(256) k_agg(const float* __restrict__ gamma,
                                             const float* __restrict__ beta,
                                             float* __restrict__ out, int N) {
    int dst = blockIdx.x * 8 + (threadIdx.x >> 5);
    int lane = threadIdx.x & 31;
    if (dst >= N) return;
    int off = g_off[dst];
    int len = g_len[dst];

    // per-relation 1/deg in lane registers (shfl-indexed)
    float invd = 0.f;
    if (lane < 8) {
        int d = g_deg[dst * 8 + lane];
        invd = 1.0f / (float)(d > 0 ? d : 1);
    }

    float a0 = 0.f, a1 = 0.f, a2 = 0.f, a3 = 0.f;
    for (int base = 0; base < len; base += 32) {
        int cnt = min(32, len - base);
        int ev = 0;
        if (lane < cnt) ev = __ldg(&g_edge[off + base + lane]);
        int i = 0;
        for (; i + 2 <= cnt; i += 2) {
            int v0 = __shfl_sync(0xffffffffu, ev, i);
            int v1 = __shfl_sync(0xffffffffu, ev, i + 1);
            int s0 = v0 >> 3, r0 = v0 & 7;
            int s1 = v1 >> 3, r1 = v1 & 7;
            uint2 h0 = *(const uint2*)(g_T + (size_t)s0 * 1024 + r0 * HIDDEN + lane * 4);
            uint2 h1 = *(const uint2*)(g_T + (size_t)s1 * 1024 + r1 * HIDDEN + lane * 4);
            float i0 = __shfl_sync(0xffffffffu, invd, r0);
            float i1 = __shfl_sync(0xffffffffu, invd, r1);
            float2 f00 = __half22float2(*(__half2*)&h0.x);
            float2 f01 = __half22float2(*(__half2*)&h0.y);
            a0 += i0 * f00.x; a1 += i0 * f00.y; a2 += i0 * f01.x; a3 += i0 * f01.y;
            float2 f10 = __half22float2(*(__half2*)&h1.x);
            float2 f11 = __half22float2(*(__half2*)&h1.y);
            a0 += i1 * f10.x; a1 += i1 * f10.y; a2 += i1 * f11.x; a3 += i1 * f11.y;
        }
        if (i < cnt) {
            int v0 = __shfl_sync(0xffffffffu, ev, i);
            int s0 = v0 >> 3, r0 = v0 & 7;
            uint2 h0 = *(const uint2*)(g_T + (size_t)s0 * 1024 + r0 * HIDDEN + lane * 4);
            float i0 = __shfl_sync(0xffffffffu, invd, r0);
            float2 f00 = __half22float2(*(__half2*)&h0.x);
            float2 f01 = __half22float2(*(__half2*)&h0.y);
            a0 += i0 * f00.x; a1 += i0 * f00.y; a2 += i0 * f01.x; a3 += i0 * f01.y;
        }
    }

    float4 s = *(const float4*)&g_out[(size_t)dst * HIDDEN + lane * 4];
    float vx = fmaxf(s.x + a0, 0.f);
    float vy = fmaxf(s.y + a1, 0.f);
    float vz = fmaxf(s.z + a2, 0.f);
    float vw = fmaxf(s.w + a3, 0.f);

    float sum = vx + vy + vz + vw;
#pragma unroll
    for (int o = 16; o > 0; o >>= 1) sum += __shfl_xor_sync(0xffffffffu, sum, o);
    float mu = sum * (1.0f / HIDDEN);
    float dx = vx - mu, dy = vy - mu, dz = vz - mu, dw = vw - mu;
    float ss = dx * dx + dy * dy + dz * dz + dw * dw;
#pragma unroll
    for (int o = 16; o > 0; o >>= 1) ss += __shfl_xor_sync(0xffffffffu, ss, o);
    float rs = rsqrtf(ss * (1.0f / HIDDEN) + 1e-5f);
    float4 gg = *(const float4*)&gamma[lane * 4];
    float4 bb = *(const float4*)&beta[lane * 4];
    float4 y = make_float4(dx * rs * gg.x + bb.x, dy * rs * gg.y + bb.y,
                           dz * rs * gg.z + bb.z, dw * rs * gg.w + bb.w);
    *(float4*)&out[(size_t)dst * HIDDEN + lane * 4] = y;
}

// ---------------- launch ----------------
extern "C" void kernel_launch(void* const* d_in, const int* in_sizes, int n_in,
                              void* d_out, int out_size) {
    const float* h     = (const float*)d_in[0];
    const void*  ei    = d_in[1];
    const void*  et    = d_in[2];
    const float* Wself = (const float*)d_in[3];
    const float* bself = (const float*)d_in[4];
    const float* Wrel  = (const float*)d_in[5];
    const float* gamma = (const float*)d_in[6];
    const float* beta  = (const float*)d_in[7];
    float* out = (float*)d_out;

    int N = in_sizes[0] / HIDDEN;
    int E = in_sizes[2];

    cudaFuncSetAttribute(k_gemm, cudaFuncAttributeMaxDynamicSharedMemorySize, GM_SMEM);

    k_init<<<256, 256>>>(Wself, Wrel, ei, N);
    k_count<<<(E + 1023) / 1024, 256>>>(ei, et, E);
    k_offsets<<<(N + 255) / 256, 256>>>(N);
    k_place<<<(E + 1023) / 1024, 256>>>(ei, et, E);

    int gblocks = (N + 127) / 128;
    k_gemm<<<gblocks, 128, GM_SMEM>>>(h, bself, N);

    int ablocks = (N + 7) / 8;
    k_agg<<<ablocks, 256>>>(gamma, beta, out, N);
}

// round 10
// speedup vs baseline: 4.8736x; 1.2178x over previous
#include <cuda_runtime.h>
#include <cuda_bf16.h>
#include <cuda_fp16.h>
#include <cstdint>

#define HIDDEN 128
#define NREL   8
#define MAXN   100000
#define MAXE   600000

// ---------------- device scratch ----------------
__device__ int   g_is64;
__device__ int   g_total;
__device__ __align__(16) int g_deg[MAXN * NREL];
__device__ int   g_mask[MAXN];     // bit r: src has outgoing edge of relation r
__device__ int   g_off[MAXN];
__device__ int   g_cur[MAXN];
__device__ int   g_len[MAXN];
__device__ int   g_edge[MAXE];     // packed (src<<3)|r
__device__ __align__(16) __half g_T[(size_t)MAXN * 1024];     // relation messages (fp16)
__device__ __align__(16) float g_out[(size_t)MAXN * HIDDEN];  // self term (fp32)
__device__ __align__(16) __half g_Bf[1152 * HIDDEN];          // [W_self; W_rel] fp16 [col][k]

// ---------------- helpers ----------------
__device__ __forceinline__ uint32_t smem_u32(const void* p) {
    uint32_t a;
    asm("{ .reg .u64 t; cvta.to.shared.u64 t, %1; cvt.u32.u64 %0, t; }" : "=r"(a) : "l"(p));
    return a;
}
__device__ __forceinline__ void ldsm4(uint32_t* r, uint32_t addr) {
    asm volatile("ldmatrix.sync.aligned.m8n8.x4.shared.b16 {%0,%1,%2,%3}, [%4];"
                 : "=r"(r[0]), "=r"(r[1]), "=r"(r[2]), "=r"(r[3]) : "r"(addr));
}
__device__ __forceinline__ void mma_f16(float* d, const uint32_t* a, const uint32_t* b) {
    asm volatile("mma.sync.aligned.m16n8k16.row.col.f32.f16.f16.f32 "
                 "{%0,%1,%2,%3}, {%4,%5,%6,%7}, {%8,%9}, {%0,%1,%2,%3};"
                 : "+f"(d[0]), "+f"(d[1]), "+f"(d[2]), "+f"(d[3])
                 : "r"(a[0]), "r"(a[1]), "r"(a[2]), "r"(a[3]), "r"(b[0]), "r"(b[1]));
}
#define CP16(dst, src) asm volatile("cp.async.cg.shared.global [%0], [%1], 16;" :: "r"(dst), "l"(src))
#define CP_COMMIT()    asm volatile("cp.async.commit_group;")

__device__ __forceinline__ int edge_val(const void* arr, int idx, int is64) {
    if (is64) return (int)((const long long*)arr)[idx];
    return ((const int*)arr)[idx];
}

// ---------------- init: detect dtype + zero deg/mask + fp16 weight pack ----------------
__global__ void k_init(const float* __restrict__ Wself, const float* __restrict__ Wrel,
                       const void* ei, int N) {
    if (blockIdx.x == 0 && threadIdx.x == 0) {
        const long long* p = (const long long*)ei;
        int ok64 = 1;
        for (int i = 0; i < 16; i++) {
            long long v = p[i];
            if (v < 0 || v >= (1LL << 31)) ok64 = 0;
        }
        g_is64 = ok64;
        g_total = 0;
    }
    int stride = gridDim.x * blockDim.x;
    int i0 = blockIdx.x * blockDim.x + threadIdx.x;
    int nd = N * NREL;
    for (int t = i0; t < nd; t += stride) g_deg[t] = 0;
    for (int t = i0; t < N; t += stride) g_mask[t] = 0;
    for (int t = i0; t < 18432; t += stride) {
        const float* src = (t < 2048) ? (Wself + (size_t)t * 8) : (Wrel + (size_t)(t - 2048) * 8);
        float4 a = *(const float4*)src;
        float4 b = *(const float4*)(src + 4);
        __half2 h0 = __floats2half2_rn(a.x, a.y);
        __half2 h1 = __floats2half2_rn(a.z, a.w);
        __half2 h2 = __floats2half2_rn(b.x, b.y);
        __half2 h3 = __floats2half2_rn(b.z, b.w);
        uint4 V = make_uint4(*(uint32_t*)&h0, *(uint32_t*)&h1, *(uint32_t*)&h2, *(uint32_t*)&h3);
        *(uint4*)(g_Bf + (size_t)t * 8) = V;
    }
}

// ---------------- degree counting + src out-relation mask ----------------
__global__ void k_count(const void* ei, const void* et, int E) {
    int is64 = g_is64;
    int base = (blockIdx.x * blockDim.x + threadIdx.x) * 4;
#pragma unroll
    for (int j = 0; j < 4; j++) {
        int e = base + j;
        if (e < E) {
            int src = edge_val(ei, e, is64);
            int dst = edge_val(ei, E + e, is64);
            int r   = edge_val(et, e, is64);
            atomicAdd(&g_deg[dst * NREL + r], 1);
            atomicOr(&g_mask[src], 1 << r);
        }
    }
}

// ---------------- CSR offsets ----------------
__global__ void k_offsets(int N) {
    int dst = blockIdx.x * blockDim.x + threadIdx.x;
    int lane = threadIdx.x & 31;
    int dd = 0;
    if (dst < N) {
        int4 a = *(const int4*)&g_deg[dst * 8];
        int4 b = *(const int4*)&g_deg[dst * 8 + 4];
        dd = a.x + a.y + a.z + a.w + b.x + b.y + b.z + b.w;
    }
    int v = dd;
#pragma unroll
    for (int o = 1; o < 32; o <<= 1) {
        int t = __shfl_up_sync(0xffffffffu, v, o);
        if (lane >= o) v += t;
    }
    int total = __shfl_sync(0xffffffffu, v, 31);
    int base = 0;
    if (lane == 31) base = atomicAdd(&g_total, total);
    base = __shfl_sync(0xffffffffu, base, 31);
    int start = base + v - dd;
    if (dst < N) {
        g_off[dst] = start;
        g_cur[dst] = start;
        g_len[dst] = dd;
    }
}

// ---------------- edge placement ----------------
__global__ void k_place(const void* ei, const void* et, int E) {
    int is64 = g_is64;
    int base = (blockIdx.x * blockDim.x + threadIdx.x) * 4;
#pragma unroll
    for (int j = 0; j < 4; j++) {
        int e = base + j;
        if (e < E) {
            int src = edge_val(ei, e, is64);
            int dst = edge_val(ei, E + e, is64);
            int r   = edge_val(et, e, is64);
            int pos = atomicAdd(&g_cur[dst], 1);
            g_edge[pos] = (src << 3) | r;
        }
    }
}

// ================= fused GEMM: [M,128] x [128,1152] fp16 =================
// CTA 128x128 tile, 4 warps (2m x 2n), warp tile 64x64. A fp16 resident (32KB),
// B dbl-buffered 32KB stages of 128 cols (9 stages). smem 96KB -> 2 CTAs/SM.
// Stage 0 (W_self) -> g_out fp32 + bias; stages 1..8 -> g_T fp16 (skipped when
// the (row, relation) block can never be read, per g_mask).
#define GM_SMEM 98304
#define GM_STAGES 9

__global__ void __launch_bounds__(128, 2) k_gemm(const float* __restrict__ h,
                                                 const float* __restrict__ bself, int M) {
    extern __shared__ char smem[];
    uint32_t sb = smem_u32(smem);
    int tid = threadIdx.x, wid = tid >> 5, lane = tid & 31;
    int bx = blockIdx.x;
    int wm = wid >> 1, wn = wid & 1;
    int g = lane >> 2, tig = lane & 3;

    auto cpB = [&](int bn, int s) {
#pragma unroll
        for (int i = 0; i < 16; i++) {
            int id = i * 128 + tid;
            int j = id >> 4, c8 = id & 15;
            const void* src = g_Bf + (size_t)(bn * 128 + j) * 128 + c8 * 8;
            uint32_t dst = sb + 32768 + s * 32768 + j * 256 + ((c8 ^ (j & 7)) << 4);
            CP16(dst, src);
        }
    };
    cpB(0, 0); CP_COMMIT();
    cpB(1, 1); CP_COMMIT();

    // A: 128 rows fp32 -> fp16 -> swizzled smem (32 KB)
#pragma unroll
    for (int i = 0; i < 32; i++) {
        int id = i * 128 + tid;
        int r = id >> 5, c4 = id & 31;
        int grow = bx * 128 + r;
        if (grow >= M) grow = M - 1;
        float4 v = *(const float4*)(h + (size_t)grow * HIDDEN + c4 * 4);
        __half2 p0 = __floats2half2_rn(v.x, v.y);
        __half2 p1 = __floats2half2_rn(v.z, v.w);
        uint2 V = make_uint2(*(uint32_t*)&p0, *(uint32_t*)&p1);
        int c8 = c4 >> 1;
        uint32_t off = r * 256 + ((c8 ^ (r & 7)) << 4) + ((c4 & 1) << 3);
        *(uint2*)(smem + off) = V;
    }

    // out-relation masks for my 8 rows
    int myrow[8], mymask[8];
#pragma unroll
    for (int mf = 0; mf < 4; mf++)
#pragma unroll
        for (int half = 0; half < 2; half++) {
            int row = bx * 128 + wm * 64 + mf * 16 + g + half * 8;
            myrow[mf * 2 + half] = row;
            mymask[mf * 2 + half] = (row < M) ? __ldg(&g_mask[row]) : 0;
        }

    for (int bn = 0; bn < GM_STAGES; bn++) {
        if (bn == GM_STAGES - 1) asm volatile("cp.async.wait_group 0;");
        else                     asm volatile("cp.async.wait_group 1;");
        __syncthreads();

        uint32_t bBase = sb + 32768 + (bn & 1) * 32768;
        float acc[4][8][4];
#pragma unroll
        for (int mf = 0; mf < 4; mf++)
#pragma unroll
            for (int nb = 0; nb < 8; nb++)
#pragma unroll
                for (int q = 0; q < 4; q++) acc[mf][nb][q] = 0.f;

#pragma unroll
        for (int ks = 0; ks < 8; ks++) {
            uint32_t af[4][4], bf[8][2];
#pragma unroll
            for (int mf = 0; mf < 4; mf++) {
                int row = wm * 64 + mf * 16 + (lane & 15);
                int c8 = ks * 2 + (lane >> 4);
                ldsm4(af[mf], sb + row * 256 + ((c8 ^ (row & 7)) << 4));
            }
#pragma unroll
            for (int p = 0; p < 4; p++) {
                int j = wn * 64 + p * 16 + (lane >> 4) * 8 + (lane & 7);
                int c8 = ks * 2 + ((lane >> 3) & 1);
                uint32_t t[4];
                ldsm4(t, bBase + j * 256 + ((c8 ^ (j & 7)) << 4));
                bf[2 * p][0] = t[0]; bf[2 * p][1] = t[1];
                bf[2 * p + 1][0] = t[2]; bf[2 * p + 1][1] = t[3];
            }
#pragma unroll
            for (int mf = 0; mf < 4; mf++)
#pragma unroll
                for (int nb = 0; nb < 8; nb++)
                    mma_f16(acc[mf][nb], af[mf], bf[nb]);
        }

        __syncthreads();
        if (bn < GM_STAGES - 2) { cpB(bn + 2, bn & 1); CP_COMMIT(); }

        int cn = wn * 64;
#pragma unroll
        for (int mf = 0; mf < 4; mf++) {
#pragma unroll
            for (int half = 0; half < 2; half++) {
                int row = myrow[mf * 2 + half];
                if (row < M) {
                    if (bn == 0) {
                        float* o = g_out + (size_t)row * HIDDEN + cn;
                        const float* bs = bself + cn;
#pragma unroll
                        for (int nb = 0; nb < 8; nb++) {
                            int col = nb * 8 + tig * 2;
                            float2 v;
                            v.x = acc[mf][nb][half * 2 + 0] + __ldg(bs + col);
                            v.y = acc[mf][nb][half * 2 + 1] + __ldg(bs + col + 1);
                            *(float2*)(o + col) = v;
                        }
                    } else if ((mymask[mf * 2 + half] >> (bn - 1)) & 1) {
                        __half* o = g_T + (size_t)row * 1024 + (bn - 1) * 128 + cn;
#pragma unroll
                        for (int nb = 0; nb < 8; nb++) {
                            int col = nb * 8 + tig * 2;
                            __half2 p = __floats2half2_rn(acc[mf][nb][half * 2 + 0],
                                                          acc[mf][nb][half * 2 + 1]);
                            *(uint32_t*)(o + col) = *(uint32_t*)&p;
                        }
                    }
                }
            }
        }
    }
}

// ---------------- aggregation + ReLU + LayerNorm (warp per node, MLP 4) ----------------
__global__ void __launch_bounds__(256) k_agg(const float* __restrict__ gamma,
                                             const float* __restrict__ beta,
                                             float* __restrict__ out, int N) {
    int dst = blockIdx.x * 8 + (threadIdx.x >> 5);
    int lane = threadIdx.x & 31;
    if (dst >= N) return;
    int off = g_off[dst];
    int len = g_len[dst];

    float invd = 0.f;
    if (lane < 8) {
        int d = g_deg[dst * 8 + lane];
        invd = 1.0f / (float)(d > 0 ? d : 1);
    }

    float a0 = 0.f, a1 = 0.f, a2 = 0.f, a3 = 0.f;
    for (int base = 0; base < len; base += 32) {
        int cnt = min(32, len - base);
        int ev = 0;
        if (lane < cnt) ev = __ldg(&g_edge[off + base + lane]);
        int i = 0;
        for (; i + 4 <= cnt; i += 4) {
            int v0 = __shfl_sync(0xffffffffu, ev, i);
            int v1 = __shfl_sync(0xffffffffu, ev, i + 1);
            int v2 = __shfl_sync(0xffffffffu, ev, i + 2);
            int v3 = __shfl_sync(0xffffffffu, ev, i + 3);
            uint2 h0 = *(const uint2*)(g_T + (size_t)(v0 >> 3) * 1024 + (v0 & 7) * HIDDEN + lane * 4);
            uint2 h1 = *(const uint2*)(g_T + (size_t)(v1 >> 3) * 1024 + (v1 & 7) * HIDDEN + lane * 4);
            uint2 h2 = *(const uint2*)(g_T + (size_t)(v2 >> 3) * 1024 + (v2 & 7) * HIDDEN + lane * 4);
            uint2 h3 = *(const uint2*)(g_T + (size_t)(v3 >> 3) * 1024 + (v3 & 7) * HIDDEN + lane * 4);
            float i0 = __shfl_sync(0xffffffffu, invd, v0 & 7);
            float i1 = __shfl_sync(0xffffffffu, invd, v1 & 7);
            float i2 = __shfl_sync(0xffffffffu, invd, v2 & 7);
            float i3 = __shfl_sync(0xffffffffu, invd, v3 & 7);
            float2 fa, fb;
            fa = __half22float2(*(__half2*)&h0.x); fb = __half22float2(*(__half2*)&h0.y);
            a0 += i0 * fa.x; a1 += i0 * fa.y; a2 += i0 * fb.x; a3 += i0 * fb.y;
            fa = __half22float2(*(__half2*)&h1.x); fb = __half22float2(*(__half2*)&h1.y);
            a0 += i1 * fa.x; a1 += i1 * fa.y; a2 += i1 * fb.x; a3 += i1 * fb.y;
            fa = __half22float2(*(__half2*)&h2.x); fb = __half22float2(*(__half2*)&h2.y);
            a0 += i2 * fa.x; a1 += i2 * fa.y; a2 += i2 * fb.x; a3 += i2 * fb.y;
            fa = __half22float2(*(__half2*)&h3.x); fb = __half22float2(*(__half2*)&h3.y);
            a0 += i3 * fa.x; a1 += i3 * fa.y; a2 += i3 * fb.x; a3 += i3 * fb.y;
        }
        for (; i < cnt; i++) {
            int v0 = __shfl_sync(0xffffffffu, ev, i);
            uint2 h0 = *(const uint2*)(g_T + (size_t)(v0 >> 3) * 1024 + (v0 & 7) * HIDDEN + lane * 4);
            float i0 = __shfl_sync(0xffffffffu, invd, v0 & 7);
            float2 fa = __half22float2(*(__half2*)&h0.x);
            float2 fb = __half22float2(*(__half2*)&h0.y);
            a0 += i0 * fa.x; a1 += i0 * fa.y; a2 += i0 * fb.x; a3 += i0 * fb.y;
        }
    }

    float4 s = *(const float4*)&g_out[(size_t)dst * HIDDEN + lane * 4];
    float vx = fmaxf(s.x + a0, 0.f);
    float vy = fmaxf(s.y + a1, 0.f);
    float vz = fmaxf(s.z + a2, 0.f);
    float vw = fmaxf(s.w + a3, 0.f);

    float sum = vx + vy + vz + vw;
#pragma unroll
    for (int o = 16; o > 0; o >>= 1) sum += __shfl_xor_sync(0xffffffffu, sum, o);
    float mu = sum * (1.0f / HIDDEN);
    float dx = vx - mu, dy = vy - mu, dz = vz - mu, dw = vw - mu;
    float ss = dx * dx + dy * dy + dz * dz + dw * dw;
#pragma unroll
    for (int o = 16; o > 0; o >>= 1) ss += __shfl_xor_sync(0xffffffffu, ss, o);
    float rs = rsqrtf(ss * (1.0f / HIDDEN) + 1e-5f);
    float4 gg = *(const float4*)&gamma[lane * 4];
    float4 bb = *(const float4*)&beta[lane * 4];
    float4 y = make_float4(dx * rs * gg.x + bb.x, dy * rs * gg.y + bb.y,
                           dz * rs * gg.z + bb.z, dw * rs * gg.w + bb.w);
    *(float4*)&out[(size_t)dst * HIDDEN + lane * 4] = y;
}

// ---------------- launch ----------------
extern "C" void kernel_launch(void* const* d_in, const int* in_sizes, int n_in,
                              void* d_out, int out_size) {
    const float* h     = (const float*)d_in[0];
    const void*  ei    = d_in[1];
    const void*  et    = d_in[2];
    const float* Wself = (const float*)d_in[3];
    const float* bself = (const float*)d_in[4];
    const float* Wrel  = (const float*)d_in[5];
    const float* gamma = (const float*)d_in[6];
    const float* beta  = (const float*)d_in[7];
    float* out = (float*)d_out;

    int N = in_sizes[0] / HIDDEN;
    int E = in_sizes[2];

    static cudaStream_t s_side = nullptr;
    static cudaEvent_t ev_fork = nullptr, ev_join = nullptr;
    if (!s_side) {
        cudaStreamCreateWithFlags(&s_side, cudaStreamNonBlocking);
        cudaEventCreateWithFlags(&ev_fork, cudaEventDisableTiming);
        cudaEventCreateWithFlags(&ev_join, cudaEventDisableTiming);
    }

    cudaFuncSetAttribute(k_gemm, cudaFuncAttributeMaxDynamicSharedMemorySize, GM_SMEM);

    // main stream: init + count (count feeds both gemm's mask and side prepass)
    k_init<<<256, 256>>>(Wself, Wrel, ei, N);
    k_count<<<(E + 1023) / 1024, 256>>>(ei, et, E);

    // fork: offsets + place on side stream, concurrent with gemm
    cudaEventRecord(ev_fork, 0);
    cudaStreamWaitEvent(s_side, ev_fork, 0);
    k_offsets<<<(N + 255) / 256, 256, 0, s_side>>>(N);
    k_place<<<(E + 1023) / 1024, 256, 0, s_side>>>(ei, et, E);
    cudaEventRecord(ev_join, s_side);

    int gblocks = (N + 127) / 128;
    k_gemm<<<gblocks, 128, GM_SMEM>>>(h, bself, N);

    // join: agg needs gemm (main) + place (side)
    cudaStreamWaitEvent(0, ev_join, 0);
    int ablocks = (N + 7) / 8;
    k_agg<<<ablocks, 256>>>(gamma, beta, out, N);
}